// round 9
// baseline (speedup 1.0000x reference)
#include <cuda_runtime.h>
#include <math.h>
#include <stdint.h>

// Problem dimensions (fixed dataset; runtime values still read from in_sizes)
#define WORD_N   50000
#define QUERY_N  50000
#define ENT_N    100000
#define REV_N    100000
#define BATCH_N  1024
#define DWDIM    64
#define DDIM     128

typedef unsigned long long u64t;

// ---------------- scratch (static __device__, no allocation) ----------------
__device__ __align__(16) float g_hq[QUERY_N * DWDIM];
__device__ __align__(16) float g_hr[REV_N * DWDIM];
__device__ __align__(16) float g_qb[BATCH_N * DWDIM];
__device__ __align__(16) float g_enth[ENT_N * DWDIM];
__device__ __align__(16) float g_degp[ENT_N];
__device__ __align__(16) float g_degi[ENT_N];
__device__ __align__(16) float g_invs[ENT_N];
__device__ __align__(16) float g_ek[ENT_N * DDIM];
__device__ __align__(16) float g_qe0[QUERY_N * DDIM];
__device__ __align__(16) float g_agg[ENT_N * DDIM];
__device__ __align__(16) float g_P[4 * 64 * 64];        // P_h = Wv[:,h16] @ Wo[h16,:]
__device__ __align__(16) float g_QKW[WORD_N * 128];     // per word: [q(64) | k(64)]
__device__ __align__(16) float g_Z[WORD_N * 256];       // per word: [h0|h1|h2|h3] = x_w @ P_h
__device__ __align__(16) unsigned int g_bitmap[4096];   // needed-entity bitmap (100K bits)

// ---------------- helpers ----------------
__device__ __forceinline__ u64t pack1(float x) {
    u64t r; asm("mov.b64 %0, {%1,%1};" : "=l"(r) : "f"(x)); return r;
}
__device__ __forceinline__ u64t ffma2(u64t a, u64t b, u64t c) {
    u64t d; asm("fma.rn.f32x2 %0, %1, %2, %3;" : "=l"(d) : "l"(a), "l"(b), "l"(c));
    return d;
}
__device__ __forceinline__ u64t pack2(float lo, float hi) {
    u64t r; asm("mov.b64 %0, {%1,%2};" : "=l"(r) : "f"(lo), "f"(hi)); return r;
}
__device__ __forceinline__ void red_add_v4(float* p, float4 v) {
    asm volatile("red.global.add.v4.f32 [%0], {%1,%2,%3,%4};"
                 :: "l"(p), "f"(v.x), "f"(v.y), "f"(v.z), "f"(v.w) : "memory");
}

// ---------------- zero scratch ----------------
__global__ void zero_kernel(int N) {
    int g = blockIdx.x * blockDim.x + threadIdx.x;
    int stride = gridDim.x * blockDim.x;
    float4 z = make_float4(0.f, 0.f, 0.f, 0.f);
    int n_agg4 = N * 32;
    for (int i = g; i < n_agg4; i += stride) ((float4*)g_agg)[i] = z;
    int n_eh4 = N * 16;
    for (int i = g; i < n_eh4; i += stride) ((float4*)g_enth)[i] = z;
    int n4 = N / 4;
    for (int i = g; i < n4; i += stride) { ((float4*)g_degp)[i] = z; ((float4*)g_degi)[i] = z; }
    if (g < 4096) g_bitmap[g] = 0u;
}

// ---------------- precompute P_h = Wv[:, h*16:(h+1)*16] @ Wo[h*16:(h+1)*16, :] ----------------
__global__ void precompute_P(const float* __restrict__ Wv, const float* __restrict__ Wo) {
    int t = blockIdx.x * blockDim.x + threadIdx.x;
    if (t >= 4 * 64 * 64) return;
    int h = t >> 12, d = (t >> 6) & 63, c = t & 63;
    float s = 0.f;
    #pragma unroll
    for (int u = 0; u < 16; u++)
        s += Wv[d * 64 + h * 16 + u] * Wo[(h * 16 + u) * 64 + c];
    g_P[t] = s;
}

// ---------------- mark needed entities from users/items/negs ----------------
__global__ void mark_needed(const int* __restrict__ users, const int* __restrict__ items,
                            const int* __restrict__ negs, int B) {
    int g = blockIdx.x * blockDim.x + threadIdx.x;
    if (g >= 3 * B) return;
    int part = g / B, b = g % B;
    int r = (part == 0) ? users[b] : ((part == 1) ? items[b] : negs[b]);
    atomicOr(&g_bitmap[r >> 5], 1u << (r & 31));
}

// ---------------- fused Z + QK precompute v2: [Z|Q|K](w) = x_w @ [P|Wq|Wk] ----------------
// 32-word tile; thread owns 4 words x 8 cols. Per d: 4 LDS.128 + 16 FFMA2.
#define XSTRIDE 34
__global__ __launch_bounds__(384) void fuse_zqk(
    const float* __restrict__ W_word, const float* __restrict__ Wq,
    const float* __restrict__ Wk, int NW)
{
    extern __shared__ char sm[];
    float* sB = (float*)sm;                      // 64*384 floats = 98304 B
    u64t* sx2 = (u64t*)(sm + 98304);             // 64*XSTRIDE u64 = 17408 B
    int t = threadIdx.x;

    for (int i = t; i < 24576; i += 384) {
        int d = i / 384, c = i % 384;
        float v;
        if (c < 256)      v = g_P[((c >> 6) << 12) + d * 64 + (c & 63)];
        else if (c < 320) v = Wq[d * 64 + (c - 256)];
        else              v = Wk[d * 64 + (c - 320)];
        sB[d * 384 + c] = v;
    }

    int tc = t % 48;           // col group: cols tc*8 .. tc*8+7
    int tw = t / 48;           // word group: words tw*4 .. tw*4+3
    int c0 = tc * 8;
    int ntiles = (NW + 31) / 32;

    for (int tile = blockIdx.x; tile < ntiles; tile += gridDim.x) {
        __syncthreads();
        for (int i = t; i < 2048; i += 384) {
            int w = i >> 6, d = i & 63;              // consecutive threads -> consecutive d
            int gw = tile * 32 + w;
            float v = W_word[(size_t)(gw < NW ? gw : 0) * 64 + d];
            sx2[d * XSTRIDE + w] = pack1(v);
        }
        __syncthreads();

        u64t acc[4][4];
        #pragma unroll
        for (int i = 0; i < 4; i++)
            #pragma unroll
            for (int p = 0; p < 4; p++) acc[i][p] = 0ULL;

        #pragma unroll 4
        for (int d = 0; d < 64; d++) {
            const float4* bp = (const float4*)(sB + d * 384 + c0);
            float4 bA = bp[0], bB = bp[1];
            u64t b0 = pack2(bA.x, bA.y), b1 = pack2(bA.z, bA.w);
            u64t b2 = pack2(bB.x, bB.y), b3 = pack2(bB.z, bB.w);
            const u64t* xr = sx2 + d * XSTRIDE + tw * 4;
            ulonglong2 xa = *(const ulonglong2*)(xr);
            ulonglong2 xb = *(const ulonglong2*)(xr + 2);
            u64t xv[4] = {xa.x, xa.y, xb.x, xb.y};
            #pragma unroll
            for (int i = 0; i < 4; i++) {
                acc[i][0] = ffma2(xv[i], b0, acc[i][0]);
                acc[i][1] = ffma2(xv[i], b1, acc[i][1]);
                acc[i][2] = ffma2(xv[i], b2, acc[i][2]);
                acc[i][3] = ffma2(xv[i], b3, acc[i][3]);
            }
        }

        int wbase = tile * 32 + tw * 4;
        #pragma unroll
        for (int i = 0; i < 4; i++) {
            int w = wbase + i;
            if (w >= NW) break;
            float* outb;
            if (c0 < 256)      outb = g_Z + (size_t)w * 256 + c0;
            else if (c0 < 320) outb = g_QKW + (size_t)w * 128 + (c0 - 256);
            else               outb = g_QKW + (size_t)w * 128 + 64 + (c0 - 320);
            *(ulonglong2*)(outb)     = make_ulonglong2(acc[i][0], acc[i][1]);
            *(ulonglong2*)(outb + 4) = make_ulonglong2(acc[i][2], acc[i][3]);
        }
    }
}

// ---------------- attention v2: smem-staged QK + Z-combine (one warp per doc) ----------------
__global__ __launch_bounds__(256)
void attn_kernel(const int* __restrict__ qids, const int* __restrict__ rids,
                 const int* __restrict__ bids, int Q, int R, int B)
{
    __shared__ float sqk[8][8 * 128];          // per warp: 8 rows x 128 floats = 4KB
    int tid = threadIdx.x, lane = tid & 31, warp = tid >> 5;
    float* sw = sqk[warp];
    int T = Q + R + B;
    int hh = lane >> 3, jj = lane & 7;
    int srow = lane >> 2, sseg = lane & 3;     // staging: 4 lanes per row

    for (int doc = blockIdx.x * 8 + warp; doc < T; doc += gridDim.x * 8) {
        const int* ids; float* outp;
        if (doc < Q)          { ids = qids + (size_t)doc * 8;       outp = g_hq + (size_t)doc * 64; }
        else if (doc < Q + R) { int r = doc - Q; ids = rids + (size_t)r * 8; outp = g_hr + (size_t)r * 64; }
        else                  { int b = doc - Q - R; ids = bids + (size_t)b * 8; outp = g_qb + (size_t)b * 64; }

        int myid = ids[jj];

        // stage this doc's 8 QK rows (4KB) cooperatively, coalesced
        {
            int rid = ids[srow];
            const float4* src = (const float4*)(g_QKW + (size_t)rid * 128);
            float4* dst = (float4*)(sw + srow * 128);
            dst[sseg * 2]     = __ldg(src + sseg * 2);
            dst[sseg * 2 + 1] = __ldg(src + sseg * 2 + 1);
            dst[8 + sseg * 2]     = __ldg(src + 8 + sseg * 2);
            dst[8 + sseg * 2 + 1] = __ldg(src + 8 + sseg * 2 + 1);
        }
        __syncwarp();

        // k vector for (head hh, key jj) from smem
        const float4* kp = (const float4*)(sw + jj * 128 + 64 + hh * 16);
        float4 k0 = kp[0], k1 = kp[1], k2 = kp[2], k3 = kp[3];

        float a_acc = 0.f;
        #pragma unroll
        for (int l = 0; l < 8; l++) {
            const float4* qp = (const float4*)(sw + l * 128 + hh * 16);
            float4 q0 = qp[0], q1 = qp[1], q2 = qp[2], q3 = qp[3];
            float s = q0.x*k0.x + q0.y*k0.y + q0.z*k0.z + q0.w*k0.w
                    + q1.x*k1.x + q1.y*k1.y + q1.z*k1.z + q1.w*k1.w
                    + q2.x*k2.x + q2.y*k2.y + q2.z*k2.z + q2.w*k2.w
                    + q3.x*k3.x + q3.y*k3.y + q3.z*k3.z + q3.w*k3.w;
            float e = __expf(s * 0.25f);
            float t = e;
            t += __shfl_xor_sync(0xffffffffu, t, 1);
            t += __shfl_xor_sync(0xffffffffu, t, 2);
            t += __shfl_xor_sync(0xffffffffu, t, 4);
            a_acc += e * __frcp_rn(t);
        }
        a_acc *= 0.125f;

        int c0 = lane * 2;
        u64t o = 0;
        #pragma unroll
        for (int j = 0; j < 8; j++) {
            int idz = __shfl_sync(0xffffffffu, myid, j);
            const float* zr = g_Z + (size_t)idz * 256 + c0;
            #pragma unroll
            for (int h = 0; h < 4; h++) {
                float av = __shfl_sync(0xffffffffu, a_acc, h * 8 + j);
                o = ffma2(pack1(av), __ldg((const u64t*)(zr + h * 64)), o);
            }
        }
        *(u64t*)(outp + c0) = o;
        __syncwarp();
    }
}

// ---------------- profile aggregation: ent_h += h_review, deg_p += 1 ----------------
__global__ void profile_kernel(const int* __restrict__ pdst, int R) {
    int g = blockIdx.x * blockDim.x + threadIdx.x;
    int r = g >> 4, q = g & 15;
    if (r >= R) return;
    int d = pdst[r];
    float4 v = *(const float4*)(g_hr + (size_t)r * 64 + q * 4);
    red_add_v4(g_enth + (size_t)d * 64 + q * 4, v);
    if (q == 0) atomicAdd(g_degp + d, 1.0f);
}

// ---------------- interaction degree ----------------
__global__ void degi_kernel(const int* __restrict__ ps, const int* __restrict__ pd, int E) {
    int g = blockIdx.x * blockDim.x + threadIdx.x;
    if (g >= E) return;
    atomicAdd(g_degi + ps[g], 1.0f);
    atomicAdd(g_degi + pd[g], 1.0f);
}

// ---------------- build e_0, q_e0, inv_sqrt ----------------
__global__ void build_kernel(const float* __restrict__ W_query,
                             const float* __restrict__ W_entity, int Q, int N) {
    int g = blockIdx.x * blockDim.x + threadIdx.x;
    int n = g >> 5, lane = g & 31;
    if (n >= N) return;
    int c = lane * 4;
    if (lane == 0) g_invs[n] = 1.0f / sqrtf(fmaxf(g_degi[n], 1.0f));
    float4 v;
    if (c < 64) {
        v = *(const float4*)(W_entity + (size_t)n * 64 + c);
    } else {
        float invdp = 1.0f / fmaxf(g_degp[n], 1.0f);
        float4 hv = *(const float4*)(g_enth + (size_t)n * 64 + (c - 64));
        v = make_float4(hv.x * invdp, hv.y * invdp, hv.z * invdp, hv.w * invdp);
    }
    *(float4*)(g_ek + (size_t)n * 128 + c) = v;
    if (n < Q) {
        float4 u;
        if (c < 64) u = *(const float4*)(W_query + (size_t)n * 64 + c);
        else        u = *(const float4*)(g_hq + (size_t)n * 64 + (c - 64));
        *(float4*)(g_qe0 + (size_t)n * 128 + c) = u;
    }
}

// ---------------- gated edge conv: warp per edge, scatter only to needed rows ----------------
__global__ void edge_gated_kernel(const int* __restrict__ ps, const int* __restrict__ pd,
                                  const int* __restrict__ pq, int E) {
    long long g = (long long)blockIdx.x * blockDim.x + threadIdx.x;
    int e = (int)(g >> 5);
    int lane = (int)(g & 31);
    if (e >= E) return;
    int src = __ldg(ps + e), dst = __ldg(pd + e);
    bool fwd = (g_bitmap[dst >> 5] >> (dst & 31)) & 1u;
    bool rev = (g_bitmap[src >> 5] >> (src & 31)) & 1u;
    if (!(fwd | rev)) return;
    int c = lane * 4;
    if (fwd) {
        int qid = __ldg(pq + e);
        float is = g_invs[src];
        float4 es = *(const float4*)(g_ek + (size_t)src * 128 + c);
        float4 qv = *(const float4*)(g_qe0 + (size_t)qid * 128 + c);
        float4 m = make_float4(es.x + qv.x * is, es.y + qv.y * is,
                               es.z + qv.z * is, es.w + qv.w * is);
        red_add_v4(g_agg + (size_t)dst * 128 + c, m);
    }
    if (rev) {
        float id = g_invs[dst];
        float4 ed = *(const float4*)(g_ek + (size_t)dst * 128 + c);
        float4 m2 = make_float4(ed.x * id, ed.y * id, ed.z * id, ed.w * id);
        red_add_v4(g_agg + (size_t)src * 128 + c, m2);
    }
}

// ---------------- output: gather e = (e0 + agg*inv)/2 at users/items/negs ----------------
__global__ void output_kernel(const int* __restrict__ users, const int* __restrict__ items,
                              const int* __restrict__ negs, int B, float* __restrict__ out) {
    int g = blockIdx.x * blockDim.x + threadIdx.x;
    int idx = g >> 5, lane = g & 31;
    if (idx >= 3 * B) return;
    int part = idx / B, b = idx % B;
    int r = (part == 0) ? users[b] : ((part == 1) ? items[b] : negs[b]);
    int c = lane * 4;
    float inv = g_invs[r];
    float4 ev = *(const float4*)(g_ek + (size_t)r * 128 + c);
    float4 av = *(const float4*)(g_agg + (size_t)r * 128 + c);
    float4 v = make_float4((ev.x + av.x * inv) * 0.5f, (ev.y + av.y * inv) * 0.5f,
                           (ev.z + av.z * inv) * 0.5f, (ev.w + av.w * inv) * 0.5f);
    if (part == 0 && c >= 64) {
        float4 qb = *(const float4*)(g_qb + (size_t)b * 64 + (c - 64));
        v.x += qb.x; v.y += qb.y; v.z += qb.z; v.w += qb.w;
    }
    *(float4*)(out + (size_t)idx * 128 + c) = v;
}

// ---------------- launch ----------------
extern "C" void kernel_launch(void* const* d_in, const int* in_sizes, int n_in,
                              void* d_out, int out_size) {
    const float* W_word   = (const float*)d_in[0];
    const float* W_query  = (const float*)d_in[1];
    const float* W_entity = (const float*)d_in[2];
    const float* Wq       = (const float*)d_in[3];
    const float* Wk       = (const float*)d_in[4];
    const float* Wv       = (const float*)d_in[5];
    const float* Wo       = (const float*)d_in[6];
    const int* qids   = (const int*)d_in[7];
    const int* rids   = (const int*)d_in[8];
    const int* pdst   = (const int*)d_in[9];
    const int* p_src  = (const int*)d_in[10];
    const int* p_dst  = (const int*)d_in[11];
    const int* p_qid  = (const int*)d_in[12];
    const int* users  = (const int*)d_in[13];
    const int* items  = (const int*)d_in[14];
    const int* negs   = (const int*)d_in[15];
    const int* qwords = (const int*)d_in[16];

    int NW = in_sizes[0] / 64;
    int Q = in_sizes[1] / 64;
    int N = in_sizes[2] / 64;
    int R = in_sizes[9];
    int E = in_sizes[10];
    int B = in_sizes[13];

    zero_kernel<<<4096, 256>>>(N);
    precompute_P<<<64, 256>>>(Wv, Wo);
    mark_needed<<<(3 * B + 255) / 256, 256>>>(users, items, negs, B);

    {
        int smem = 98304 + 17408;   // 115712 B
        cudaFuncSetAttribute(fuse_zqk, cudaFuncAttributeMaxDynamicSharedMemorySize, smem);
        int ntiles = (NW + 31) / 32;
        fuse_zqk<<<ntiles < 592 ? ntiles : 592, 384, smem>>>(W_word, Wq, Wk, NW);
    }

    attn_kernel<<<1184, 256>>>(qids, rids, qwords, Q, R, B);

    profile_kernel<<<(R * 16 + 255) / 256, 256>>>(pdst, R);
    degi_kernel<<<(E + 255) / 256, 256>>>(p_src, p_dst, E);
    build_kernel<<<(N * 32 + 255) / 256, 256>>>(W_query, W_entity, Q, N);

    long long ethreads = (long long)E * 32;
    edge_gated_kernel<<<(int)((ethreads + 255) / 256), 256>>>(p_src, p_dst, p_qid, E);

    output_kernel<<<(3 * B * 32 + 255) / 256, 256>>>(users, items, negs, B, (float*)d_out);
}

// round 10
// speedup vs baseline: 1.0381x; 1.0381x over previous
#include <cuda_runtime.h>
#include <math.h>
#include <stdint.h>

// Problem dimensions (fixed dataset; runtime values still read from in_sizes)
#define WORD_N   50000
#define QUERY_N  50000
#define ENT_N    100000
#define REV_N    100000
#define BATCH_N  1024
#define DWDIM    64
#define DDIM     128

typedef unsigned long long u64t;

// ---------------- scratch (static __device__, no allocation) ----------------
__device__ __align__(16) float g_hq[QUERY_N * DWDIM];
__device__ __align__(16) float g_hr[REV_N * DWDIM];
__device__ __align__(16) float g_qb[BATCH_N * DWDIM];
__device__ __align__(16) float g_enth[ENT_N * DWDIM];
__device__ __align__(16) float g_degp[ENT_N];
__device__ __align__(16) float g_degi[ENT_N];
__device__ __align__(16) float g_invs[ENT_N];
__device__ __align__(16) float g_ek[ENT_N * DDIM];
__device__ __align__(16) float g_qe0[QUERY_N * DDIM];
__device__ __align__(16) float g_agg[ENT_N * DDIM];
__device__ __align__(16) float g_P[4 * 64 * 64];        // P_h = Wv[:,h16] @ Wo[h16,:]
__device__ __align__(16) float g_QKW[WORD_N * 128];     // per word: [q(64) | k(64)]
__device__ __align__(16) float g_Z[WORD_N * 256];       // per word: [h0|h1|h2|h3] = x_w @ P_h
__device__ __align__(16) unsigned int g_bitmap[4096];   // needed-entity bitmap (100K bits)

// ---------------- helpers ----------------
__device__ __forceinline__ u64t pack1(float x) {
    u64t r; asm("mov.b64 %0, {%1,%1};" : "=l"(r) : "f"(x)); return r;
}
__device__ __forceinline__ u64t ffma2(u64t a, u64t b, u64t c) {
    u64t d; asm("fma.rn.f32x2 %0, %1, %2, %3;" : "=l"(d) : "l"(a), "l"(b), "l"(c));
    return d;
}
__device__ __forceinline__ void red_add_v4(float* p, float4 v) {
    asm volatile("red.global.add.v4.f32 [%0], {%1,%2,%3,%4};"
                 :: "l"(p), "f"(v.x), "f"(v.y), "f"(v.z), "f"(v.w) : "memory");
}

// ---------------- zero scratch ----------------
__global__ void zero_kernel(int N) {
    int g = blockIdx.x * blockDim.x + threadIdx.x;
    int stride = gridDim.x * blockDim.x;
    float4 z = make_float4(0.f, 0.f, 0.f, 0.f);
    int n_agg4 = N * 32;
    for (int i = g; i < n_agg4; i += stride) ((float4*)g_agg)[i] = z;
    int n_eh4 = N * 16;
    for (int i = g; i < n_eh4; i += stride) ((float4*)g_enth)[i] = z;
    int n4 = N / 4;
    for (int i = g; i < n4; i += stride) { ((float4*)g_degp)[i] = z; ((float4*)g_degi)[i] = z; }
    if (g < 4096) g_bitmap[g] = 0u;
}

// ---------------- precompute P_h = Wv[:, h*16:(h+1)*16] @ Wo[h*16:(h+1)*16, :] ----------------
__global__ void precompute_P(const float* __restrict__ Wv, const float* __restrict__ Wo) {
    int t = blockIdx.x * blockDim.x + threadIdx.x;
    if (t >= 4 * 64 * 64) return;
    int h = t >> 12, d = (t >> 6) & 63, c = t & 63;
    float s = 0.f;
    #pragma unroll
    for (int u = 0; u < 16; u++)
        s += Wv[d * 64 + h * 16 + u] * Wo[(h * 16 + u) * 64 + c];
    g_P[t] = s;
}

// ---------------- mark needed entities from users/items/negs ----------------
__global__ void mark_needed(const int* __restrict__ users, const int* __restrict__ items,
                            const int* __restrict__ negs, int B) {
    int g = blockIdx.x * blockDim.x + threadIdx.x;
    if (g >= 3 * B) return;
    int part = g / B, b = g % B;
    int r = (part == 0) ? users[b] : ((part == 1) ? items[b] : negs[b]);
    atomicOr(&g_bitmap[r >> 5], 1u << (r & 31));
}

// ---------------- fused Z + QK precompute v3: [Z|Q|K](w) = x_w @ [P|Wq|Wk] ----------------
// 32-word tile; thread owns 4 words x 2 col-quads (cols [4tc,4tc+4) and [192+4tc,+4)).
// B loaded as ulonglong2 directly (u64 halves ARE adjacent col-pairs): no repack,
// 16B lane stride -> conflict-free 4-phase LDS.128.
#define XSTRIDE 34
__global__ __launch_bounds__(384) void fuse_zqk(
    const float* __restrict__ W_word, const float* __restrict__ Wq,
    const float* __restrict__ Wk, int NW)
{
    extern __shared__ char sm[];
    float* sB = (float*)sm;                      // 64*384 floats = 98304 B
    u64t* sx2 = (u64t*)(sm + 98304);             // 64*XSTRIDE u64 = 17408 B
    int t = threadIdx.x;

    for (int i = t; i < 24576; i += 384) {
        int d = i / 384, c = i % 384;
        float v;
        if (c < 256)      v = g_P[((c >> 6) << 12) + d * 64 + (c & 63)];
        else if (c < 320) v = Wq[d * 64 + (c - 256)];
        else              v = Wk[d * 64 + (c - 320)];
        sB[d * 384 + c] = v;
    }

    int tc = t % 48;           // col-quad index
    int tw = t / 48;           // word group: words tw*4 .. tw*4+3
    int cA = tc * 4;           // quad A: cols [cA, cA+4)   in [0,192)
    int cB = 192 + tc * 4;     // quad B: cols [cB, cB+4)   in [192,384)
    int ntiles = (NW + 31) / 32;

    for (int tile = blockIdx.x; tile < ntiles; tile += gridDim.x) {
        __syncthreads();
        for (int i = t; i < 2048; i += 384) {
            int w = i >> 6, d = i & 63;
            int gw = tile * 32 + w;
            float v = W_word[(size_t)(gw < NW ? gw : 0) * 64 + d];
            sx2[d * XSTRIDE + w] = pack1(v);
        }
        __syncthreads();

        u64t acc[4][4];
        #pragma unroll
        for (int i = 0; i < 4; i++)
            #pragma unroll
            for (int p = 0; p < 4; p++) acc[i][p] = 0ULL;

        #pragma unroll 4
        for (int d = 0; d < 64; d++) {
            ulonglong2 bA = *(const ulonglong2*)(sB + d * 384 + cA);  // pairs (cA,cA+1),(cA+2,cA+3)
            ulonglong2 bB = *(const ulonglong2*)(sB + d * 384 + cB);
            const u64t* xr = sx2 + d * XSTRIDE + tw * 4;
            ulonglong2 xa = *(const ulonglong2*)(xr);
            ulonglong2 xb = *(const ulonglong2*)(xr + 2);
            u64t xv[4] = {xa.x, xa.y, xb.x, xb.y};
            #pragma unroll
            for (int i = 0; i < 4; i++) {
                acc[i][0] = ffma2(xv[i], bA.x, acc[i][0]);
                acc[i][1] = ffma2(xv[i], bA.y, acc[i][1]);
                acc[i][2] = ffma2(xv[i], bB.x, acc[i][2]);
                acc[i][3] = ffma2(xv[i], bB.y, acc[i][3]);
            }
        }

        int wbase = tile * 32 + tw * 4;
        #pragma unroll
        for (int i = 0; i < 4; i++) {
            int w = wbase + i;
            if (w >= NW) break;
            // quad A (cols cA..cA+3): always within Z (cA < 192 < 256)
            *(ulonglong2*)(g_Z + (size_t)w * 256 + cA) = make_ulonglong2(acc[i][0], acc[i][1]);
            // quad B: region determined by cB (never straddles 256/320)
            float* outb;
            if (cB < 256)      outb = g_Z + (size_t)w * 256 + cB;
            else if (cB < 320) outb = g_QKW + (size_t)w * 128 + (cB - 256);
            else               outb = g_QKW + (size_t)w * 128 + 64 + (cB - 320);
            *(ulonglong2*)(outb) = make_ulonglong2(acc[i][2], acc[i][3]);
        }
    }
}

// ---------------- attention: scores + softmax + Z-combine (one warp per doc) ----------------
// (round-8 version, verified rel_err 8.7e-8)
__global__ __launch_bounds__(256)
void attn_kernel(const int* __restrict__ qids, const int* __restrict__ rids,
                 const int* __restrict__ bids, int Q, int R, int B)
{
    int tid = threadIdx.x, lane = tid & 31, warp = tid >> 5;
    int T = Q + R + B;
    int hh = lane >> 3, jj = lane & 7;

    for (int doc = blockIdx.x * 8 + warp; doc < T; doc += gridDim.x * 8) {
        const int* ids; float* outp;
        if (doc < Q)          { ids = qids + (size_t)doc * 8;       outp = g_hq + (size_t)doc * 64; }
        else if (doc < Q + R) { int r = doc - Q; ids = rids + (size_t)r * 8; outp = g_hr + (size_t)r * 64; }
        else                  { int b = doc - Q - R; ids = bids + (size_t)b * 8; outp = g_qb + (size_t)b * 64; }

        int myid = ids[jj];

        const float4* kp = (const float4*)(g_QKW + (size_t)myid * 128 + 64 + hh * 16);
        float4 k0 = __ldg(kp), k1 = __ldg(kp + 1), k2 = __ldg(kp + 2), k3 = __ldg(kp + 3);

        float a_acc = 0.f;
        #pragma unroll
        for (int l = 0; l < 8; l++) {
            int idl = __shfl_sync(0xffffffffu, myid, l);
            const float4* qp = (const float4*)(g_QKW + (size_t)idl * 128 + hh * 16);
            float4 q0 = __ldg(qp), q1 = __ldg(qp + 1), q2 = __ldg(qp + 2), q3 = __ldg(qp + 3);
            float s = q0.x*k0.x + q0.y*k0.y + q0.z*k0.z + q0.w*k0.w
                    + q1.x*k1.x + q1.y*k1.y + q1.z*k1.z + q1.w*k1.w
                    + q2.x*k2.x + q2.y*k2.y + q2.z*k2.z + q2.w*k2.w
                    + q3.x*k3.x + q3.y*k3.y + q3.z*k3.z + q3.w*k3.w;
            float e = __expf(s * 0.25f);
            float t = e;
            t += __shfl_xor_sync(0xffffffffu, t, 1);
            t += __shfl_xor_sync(0xffffffffu, t, 2);
            t += __shfl_xor_sync(0xffffffffu, t, 4);
            a_acc += e * __frcp_rn(t);
        }
        a_acc *= 0.125f;

        int c0 = lane * 2;
        u64t o = 0;
        #pragma unroll
        for (int j = 0; j < 8; j++) {
            int idz = __shfl_sync(0xffffffffu, myid, j);
            const float* zr = g_Z + (size_t)idz * 256 + c0;
            #pragma unroll
            for (int h = 0; h < 4; h++) {
                float av = __shfl_sync(0xffffffffu, a_acc, h * 8 + j);
                o = ffma2(pack1(av), __ldg((const u64t*)(zr + h * 64)), o);
            }
        }
        *(u64t*)(outp + c0) = o;
        __syncwarp();
    }
}

// ---------------- profile aggregation: ent_h += h_review, deg_p += 1 ----------------
__global__ void profile_kernel(const int* __restrict__ pdst, int R) {
    int g = blockIdx.x * blockDim.x + threadIdx.x;
    int r = g >> 4, q = g & 15;
    if (r >= R) return;
    int d = pdst[r];
    float4 v = *(const float4*)(g_hr + (size_t)r * 64 + q * 4);
    red_add_v4(g_enth + (size_t)d * 64 + q * 4, v);
    if (q == 0) atomicAdd(g_degp + d, 1.0f);
}

// ---------------- interaction degree ----------------
__global__ void degi_kernel(const int* __restrict__ ps, const int* __restrict__ pd, int E) {
    int g = blockIdx.x * blockDim.x + threadIdx.x;
    if (g >= E) return;
    atomicAdd(g_degi + ps[g], 1.0f);
    atomicAdd(g_degi + pd[g], 1.0f);
}

// ---------------- build e_0, q_e0, inv_sqrt ----------------
__global__ void build_kernel(const float* __restrict__ W_query,
                             const float* __restrict__ W_entity, int Q, int N) {
    int g = blockIdx.x * blockDim.x + threadIdx.x;
    int n = g >> 5, lane = g & 31;
    if (n >= N) return;
    int c = lane * 4;
    if (lane == 0) g_invs[n] = 1.0f / sqrtf(fmaxf(g_degi[n], 1.0f));
    float4 v;
    if (c < 64) {
        v = *(const float4*)(W_entity + (size_t)n * 64 + c);
    } else {
        float invdp = 1.0f / fmaxf(g_degp[n], 1.0f);
        float4 hv = *(const float4*)(g_enth + (size_t)n * 64 + (c - 64));
        v = make_float4(hv.x * invdp, hv.y * invdp, hv.z * invdp, hv.w * invdp);
    }
    *(float4*)(g_ek + (size_t)n * 128 + c) = v;
    if (n < Q) {
        float4 u;
        if (c < 64) u = *(const float4*)(W_query + (size_t)n * 64 + c);
        else        u = *(const float4*)(g_hq + (size_t)n * 64 + (c - 64));
        *(float4*)(g_qe0 + (size_t)n * 128 + c) = u;
    }
}

// ---------------- gated edge conv: warp per edge, scatter only to needed rows ----------------
__global__ void edge_gated_kernel(const int* __restrict__ ps, const int* __restrict__ pd,
                                  const int* __restrict__ pq, int E) {
    long long g = (long long)blockIdx.x * blockDim.x + threadIdx.x;
    int e = (int)(g >> 5);
    int lane = (int)(g & 31);
    if (e >= E) return;
    int src = __ldg(ps + e), dst = __ldg(pd + e);
    bool fwd = (g_bitmap[dst >> 5] >> (dst & 31)) & 1u;
    bool rev = (g_bitmap[src >> 5] >> (src & 31)) & 1u;
    if (!(fwd | rev)) return;
    int c = lane * 4;
    if (fwd) {
        int qid = __ldg(pq + e);
        float is = g_invs[src];
        float4 es = *(const float4*)(g_ek + (size_t)src * 128 + c);
        float4 qv = *(const float4*)(g_qe0 + (size_t)qid * 128 + c);
        float4 m = make_float4(es.x + qv.x * is, es.y + qv.y * is,
                               es.z + qv.z * is, es.w + qv.w * is);
        red_add_v4(g_agg + (size_t)dst * 128 + c, m);
    }
    if (rev) {
        float id = g_invs[dst];
        float4 ed = *(const float4*)(g_ek + (size_t)dst * 128 + c);
        float4 m2 = make_float4(ed.x * id, ed.y * id, ed.z * id, ed.w * id);
        red_add_v4(g_agg + (size_t)src * 128 + c, m2);
    }
}

// ---------------- output: gather e = (e0 + agg*inv)/2 at users/items/negs ----------------
__global__ void output_kernel(const int* __restrict__ users, const int* __restrict__ items,
                              const int* __restrict__ negs, int B, float* __restrict__ out) {
    int g = blockIdx.x * blockDim.x + threadIdx.x;
    int idx = g >> 5, lane = g & 31;
    if (idx >= 3 * B) return;
    int part = idx / B, b = idx % B;
    int r = (part == 0) ? users[b] : ((part == 1) ? items[b] : negs[b]);
    int c = lane * 4;
    float inv = g_invs[r];
    float4 ev = *(const float4*)(g_ek + (size_t)r * 128 + c);
    float4 av = *(const float4*)(g_agg + (size_t)r * 128 + c);
    float4 v = make_float4((ev.x + av.x * inv) * 0.5f, (ev.y + av.y * inv) * 0.5f,
                           (ev.z + av.z * inv) * 0.5f, (ev.w + av.w * inv) * 0.5f);
    if (part == 0 && c >= 64) {
        float4 qb = *(const float4*)(g_qb + (size_t)b * 64 + (c - 64));
        v.x += qb.x; v.y += qb.y; v.z += qb.z; v.w += qb.w;
    }
    *(float4*)(out + (size_t)idx * 128 + c) = v;
}

// ---------------- launch ----------------
extern "C" void kernel_launch(void* const* d_in, const int* in_sizes, int n_in,
                              void* d_out, int out_size) {
    const float* W_word   = (const float*)d_in[0];
    const float* W_query  = (const float*)d_in[1];
    const float* W_entity = (const float*)d_in[2];
    const float* Wq       = (const float*)d_in[3];
    const float* Wk       = (const float*)d_in[4];
    const float* Wv       = (const float*)d_in[5];
    const float* Wo       = (const float*)d_in[6];
    const int* qids   = (const int*)d_in[7];
    const int* rids   = (const int*)d_in[8];
    const int* pdst   = (const int*)d_in[9];
    const int* p_src  = (const int*)d_in[10];
    const int* p_dst  = (const int*)d_in[11];
    const int* p_qid  = (const int*)d_in[12];
    const int* users  = (const int*)d_in[13];
    const int* items  = (const int*)d_in[14];
    const int* negs   = (const int*)d_in[15];
    const int* qwords = (const int*)d_in[16];

    int NW = in_sizes[0] / 64;
    int Q = in_sizes[1] / 64;
    int N = in_sizes[2] / 64;
    int R = in_sizes[9];
    int E = in_sizes[10];
    int B = in_sizes[13];

    zero_kernel<<<4096, 256>>>(N);
    precompute_P<<<64, 256>>>(Wv, Wo);
    mark_needed<<<(3 * B + 255) / 256, 256>>>(users, items, negs, B);

    {
        int smem = 98304 + 17408;   // 115712 B
        cudaFuncSetAttribute(fuse_zqk, cudaFuncAttributeMaxDynamicSharedMemorySize, smem);
        int ntiles = (NW + 31) / 32;
        fuse_zqk<<<ntiles < 592 ? ntiles : 592, 384, smem>>>(W_word, Wq, Wk, NW);
    }

    attn_kernel<<<1184, 256>>>(qids, rids, qwords, Q, R, B);

    profile_kernel<<<(R * 16 + 255) / 256, 256>>>(pdst, R);
    degi_kernel<<<(E + 255) / 256, 256>>>(p_src, p_dst, E);
    build_kernel<<<(N * 32 + 255) / 256, 256>>>(W_query, W_entity, Q, N);

    long long ethreads = (long long)E * 32;
    edge_gated_kernel<<<(int)((ethreads + 255) / 256), 256>>>(p_src, p_dst, p_qid, E);

    output_kernel<<<(3 * B * 32 + 255) / 256, 256>>>(users, items, negs, B, (float*)d_out);
}

// round 11
// speedup vs baseline: 1.4610x; 1.4073x over previous
#include <cuda_runtime.h>
#include <math.h>
#include <stdint.h>

// Problem dimensions (fixed dataset; runtime values still read from in_sizes)
#define WORD_N   50000
#define QUERY_N  50000
#define ENT_N    100000
#define REV_N    100000
#define EDGE_N   2000000
#define BATCH_N  1024
#define DWDIM    64
#define DDIM     128

typedef unsigned long long u64t;

// ---------------- scratch (static __device__, no allocation) ----------------
__device__ __align__(16) float g_hq[QUERY_N * DWDIM];
__device__ __align__(16) float g_hr[REV_N * DWDIM];
__device__ __align__(16) float g_qb[BATCH_N * DWDIM];
__device__ __align__(16) float g_enth[ENT_N * DWDIM];
__device__ __align__(16) float g_degp[ENT_N];
__device__ __align__(16) float g_degi[ENT_N];
__device__ __align__(16) float g_invs[ENT_N];
__device__ __align__(16) float g_ek[ENT_N * DDIM];
__device__ __align__(16) float g_qe0[QUERY_N * DDIM];
__device__ __align__(16) float g_agg[ENT_N * DDIM];
__device__ __align__(16) float g_P[4 * 64 * 64];        // P_h = Wv[:,h16] @ Wo[h16,:]
__device__ __align__(16) float g_QKW[WORD_N * 128];     // per word: [q(64) | k(64)]
__device__ __align__(16) float g_Z[WORD_N * 256];       // per word: [h0|h1|h2|h3] = x_w @ P_h
__device__ __align__(16) unsigned int g_bitmap[4096];   // needed-entity bitmap (100K bits)
__device__ int g_ecount;
__device__ __align__(16) unsigned int g_elist[EDGE_N];  // compact hit edges (flags in bits 30-31)

// ---------------- helpers ----------------
__device__ __forceinline__ u64t pack1(float x) {
    u64t r; asm("mov.b64 %0, {%1,%1};" : "=l"(r) : "f"(x)); return r;
}
__device__ __forceinline__ u64t ffma2(u64t a, u64t b, u64t c) {
    u64t d; asm("fma.rn.f32x2 %0, %1, %2, %3;" : "=l"(d) : "l"(a), "l"(b), "l"(c));
    return d;
}
__device__ __forceinline__ void red_add_v4(float* p, float4 v) {
    asm volatile("red.global.add.v4.f32 [%0], {%1,%2,%3,%4};"
                 :: "l"(p), "f"(v.x), "f"(v.y), "f"(v.z), "f"(v.w) : "memory");
}

// ---------------- zero scratch ----------------
__global__ void zero_kernel(int N) {
    int g = blockIdx.x * blockDim.x + threadIdx.x;
    int stride = gridDim.x * blockDim.x;
    float4 z = make_float4(0.f, 0.f, 0.f, 0.f);
    int n_agg4 = N * 32;
    for (int i = g; i < n_agg4; i += stride) ((float4*)g_agg)[i] = z;
    int n_eh4 = N * 16;
    for (int i = g; i < n_eh4; i += stride) ((float4*)g_enth)[i] = z;
    int n4 = N / 4;
    for (int i = g; i < n4; i += stride) { ((float4*)g_degp)[i] = z; ((float4*)g_degi)[i] = z; }
    if (g < 4096) g_bitmap[g] = 0u;
    if (g == 0) g_ecount = 0;
}

// ---------------- precompute P_h = Wv[:, h*16:(h+1)*16] @ Wo[h*16:(h+1)*16, :] ----------------
__global__ void precompute_P(const float* __restrict__ Wv, const float* __restrict__ Wo) {
    int t = blockIdx.x * blockDim.x + threadIdx.x;
    if (t >= 4 * 64 * 64) return;
    int h = t >> 12, d = (t >> 6) & 63, c = t & 63;
    float s = 0.f;
    #pragma unroll
    for (int u = 0; u < 16; u++)
        s += Wv[d * 64 + h * 16 + u] * Wo[(h * 16 + u) * 64 + c];
    g_P[t] = s;
}

// ---------------- mark needed entities from users/items/negs ----------------
__global__ void mark_needed(const int* __restrict__ users, const int* __restrict__ items,
                            const int* __restrict__ negs, int B) {
    int g = blockIdx.x * blockDim.x + threadIdx.x;
    if (g >= 3 * B) return;
    int part = g / B, b = g % B;
    int r = (part == 0) ? users[b] : ((part == 1) ? items[b] : negs[b]);
    atomicOr(&g_bitmap[r >> 5], 1u << (r & 31));
}

// ---------------- fused Z + QK precompute v3 (unchanged from round 10) ----------------
#define XSTRIDE 34
__global__ __launch_bounds__(384) void fuse_zqk(
    const float* __restrict__ W_word, const float* __restrict__ Wq,
    const float* __restrict__ Wk, int NW)
{
    extern __shared__ char sm[];
    float* sB = (float*)sm;                      // 64*384 floats = 98304 B
    u64t* sx2 = (u64t*)(sm + 98304);             // 64*XSTRIDE u64 = 17408 B
    int t = threadIdx.x;

    for (int i = t; i < 24576; i += 384) {
        int d = i / 384, c = i % 384;
        float v;
        if (c < 256)      v = g_P[((c >> 6) << 12) + d * 64 + (c & 63)];
        else if (c < 320) v = Wq[d * 64 + (c - 256)];
        else              v = Wk[d * 64 + (c - 320)];
        sB[d * 384 + c] = v;
    }

    int tc = t % 48;
    int tw = t / 48;
    int cA = tc * 4;
    int cB = 192 + tc * 4;
    int ntiles = (NW + 31) / 32;

    for (int tile = blockIdx.x; tile < ntiles; tile += gridDim.x) {
        __syncthreads();
        for (int i = t; i < 2048; i += 384) {
            int w = i >> 6, d = i & 63;
            int gw = tile * 32 + w;
            float v = W_word[(size_t)(gw < NW ? gw : 0) * 64 + d];
            sx2[d * XSTRIDE + w] = pack1(v);
        }
        __syncthreads();

        u64t acc[4][4];
        #pragma unroll
        for (int i = 0; i < 4; i++)
            #pragma unroll
            for (int p = 0; p < 4; p++) acc[i][p] = 0ULL;

        #pragma unroll 4
        for (int d = 0; d < 64; d++) {
            ulonglong2 bA = *(const ulonglong2*)(sB + d * 384 + cA);
            ulonglong2 bB = *(const ulonglong2*)(sB + d * 384 + cB);
            const u64t* xr = sx2 + d * XSTRIDE + tw * 4;
            ulonglong2 xa = *(const ulonglong2*)(xr);
            ulonglong2 xb = *(const ulonglong2*)(xr + 2);
            u64t xv[4] = {xa.x, xa.y, xb.x, xb.y};
            #pragma unroll
            for (int i = 0; i < 4; i++) {
                acc[i][0] = ffma2(xv[i], bA.x, acc[i][0]);
                acc[i][1] = ffma2(xv[i], bA.y, acc[i][1]);
                acc[i][2] = ffma2(xv[i], bB.x, acc[i][2]);
                acc[i][3] = ffma2(xv[i], bB.y, acc[i][3]);
            }
        }

        int wbase = tile * 32 + tw * 4;
        #pragma unroll
        for (int i = 0; i < 4; i++) {
            int w = wbase + i;
            if (w >= NW) break;
            *(ulonglong2*)(g_Z + (size_t)w * 256 + cA) = make_ulonglong2(acc[i][0], acc[i][1]);
            float* outb;
            if (cB < 256)      outb = g_Z + (size_t)w * 256 + cB;
            else if (cB < 320) outb = g_QKW + (size_t)w * 128 + (cB - 256);
            else               outb = g_QKW + (size_t)w * 128 + 64 + (cB - 320);
            *(ulonglong2*)(outb) = make_ulonglong2(acc[i][2], acc[i][3]);
        }
    }
}

// ---------------- attention v3: padded smem-staged QK + Z-combine ----------------
#define QKROW 132     // 128 data floats + 4 pad -> conflict-free k-phase
__global__ __launch_bounds__(256)
void attn_kernel(const int* __restrict__ qids, const int* __restrict__ rids,
                 const int* __restrict__ bids, int Q, int R, int B)
{
    __shared__ float sqk[8][8 * QKROW];        // per warp: 8 rows x 132 floats = 4224 B
    int tid = threadIdx.x, lane = tid & 31, warp = tid >> 5;
    float* sw = sqk[warp];
    int T = Q + R + B;
    int hh = lane >> 3, jj = lane & 7;
    int srow = lane >> 2, sseg = lane & 3;     // staging: 4 lanes per row

    for (int doc = blockIdx.x * 8 + warp; doc < T; doc += gridDim.x * 8) {
        const int* ids; float* outp;
        if (doc < Q)          { ids = qids + (size_t)doc * 8;       outp = g_hq + (size_t)doc * 64; }
        else if (doc < Q + R) { int r = doc - Q; ids = rids + (size_t)r * 8; outp = g_hr + (size_t)r * 64; }
        else                  { int b = doc - Q - R; ids = bids + (size_t)b * 8; outp = g_qb + (size_t)b * 64; }

        int myid = ids[jj];

        // stage this doc's 8 QK rows (ALL 32 float4 per row), 4 lanes/row
        {
            int rid = ids[srow];
            const float4* src = (const float4*)(g_QKW + (size_t)rid * 128);
            float4* dst = (float4*)(sw + srow * QKROW);
            #pragma unroll
            for (int p = 0; p < 4; p++) {
                dst[p * 8 + sseg * 2]     = __ldg(src + p * 8 + sseg * 2);
                dst[p * 8 + sseg * 2 + 1] = __ldg(src + p * 8 + sseg * 2 + 1);
            }
        }
        __syncwarp();

        // k vector for (head hh, key jj) from smem (conflict-free via pad)
        const float4* kp = (const float4*)(sw + jj * QKROW + 64 + hh * 16);
        float4 k0 = kp[0], k1 = kp[1], k2 = kp[2], k3 = kp[3];

        float a_acc = 0.f;
        #pragma unroll
        for (int l = 0; l < 8; l++) {
            const float4* qp = (const float4*)(sw + l * QKROW + hh * 16);  // 8-lane broadcast
            float4 q0 = qp[0], q1 = qp[1], q2 = qp[2], q3 = qp[3];
            float s = q0.x*k0.x + q0.y*k0.y + q0.z*k0.z + q0.w*k0.w
                    + q1.x*k1.x + q1.y*k1.y + q1.z*k1.z + q1.w*k1.w
                    + q2.x*k2.x + q2.y*k2.y + q2.z*k2.z + q2.w*k2.w
                    + q3.x*k3.x + q3.y*k3.y + q3.z*k3.z + q3.w*k3.w;
            float e = __expf(s * 0.25f);
            float t = e;
            t += __shfl_xor_sync(0xffffffffu, t, 1);
            t += __shfl_xor_sync(0xffffffffu, t, 2);
            t += __shfl_xor_sync(0xffffffffu, t, 4);
            a_acc += e * __frcp_rn(t);
        }
        a_acc *= 0.125f;

        int c0 = lane * 2;
        u64t o = 0;
        #pragma unroll
        for (int j = 0; j < 8; j++) {
            int idz = __shfl_sync(0xffffffffu, myid, j);
            const float* zr = g_Z + (size_t)idz * 256 + c0;
            #pragma unroll
            for (int h = 0; h < 4; h++) {
                float av = __shfl_sync(0xffffffffu, a_acc, h * 8 + j);
                o = ffma2(pack1(av), __ldg((const u64t*)(zr + h * 64)), o);
            }
        }
        *(u64t*)(outp + c0) = o;
        __syncwarp();
    }
}

// ---------------- profile aggregation: ent_h += h_review, deg_p += 1 ----------------
__global__ void profile_kernel(const int* __restrict__ pdst, int R) {
    int g = blockIdx.x * blockDim.x + threadIdx.x;
    int r = g >> 4, q = g & 15;
    if (r >= R) return;
    int d = pdst[r];
    float4 v = *(const float4*)(g_hr + (size_t)r * 64 + q * 4);
    red_add_v4(g_enth + (size_t)d * 64 + q * 4, v);
    if (q == 0) atomicAdd(g_degp + d, 1.0f);
}

// ---------------- edge scan: degi + bitmap test + compact hit list (1 thread/edge) ----------------
__global__ void edge_scan_kernel(const int* __restrict__ ps, const int* __restrict__ pd, int E) {
    int e = blockIdx.x * blockDim.x + threadIdx.x;
    if (e >= E) return;
    int s = __ldg(ps + e), d = __ldg(pd + e);
    atomicAdd(g_degi + s, 1.0f);
    atomicAdd(g_degi + d, 1.0f);
    unsigned f = ((g_bitmap[d >> 5] >> (d & 31)) & 1u)
               | (((g_bitmap[s >> 5] >> (s & 31)) & 1u) << 1);
    if (f) {
        int idx = atomicAdd(&g_ecount, 1);
        g_elist[idx] = (unsigned)e | (f << 30);
    }
}

// ---------------- build e_0, q_e0, inv_sqrt ----------------
__global__ void build_kernel(const float* __restrict__ W_query,
                             const float* __restrict__ W_entity, int Q, int N) {
    int g = blockIdx.x * blockDim.x + threadIdx.x;
    int n = g >> 5, lane = g & 31;
    if (n >= N) return;
    int c = lane * 4;
    if (lane == 0) g_invs[n] = 1.0f / sqrtf(fmaxf(g_degi[n], 1.0f));
    float4 v;
    if (c < 64) {
        v = *(const float4*)(W_entity + (size_t)n * 64 + c);
    } else {
        float invdp = 1.0f / fmaxf(g_degp[n], 1.0f);
        float4 hv = *(const float4*)(g_enth + (size_t)n * 64 + (c - 64));
        v = make_float4(hv.x * invdp, hv.y * invdp, hv.z * invdp, hv.w * invdp);
    }
    *(float4*)(g_ek + (size_t)n * 128 + c) = v;
    if (n < Q) {
        float4 u;
        if (c < 64) u = *(const float4*)(W_query + (size_t)n * 64 + c);
        else        u = *(const float4*)(g_hq + (size_t)n * 64 + (c - 64));
        *(float4*)(g_qe0 + (size_t)n * 128 + c) = u;
    }
}

// ---------------- edge apply: warp per compact hit entry (grid-stride) ----------------
__global__ void edge_apply_kernel(const int* __restrict__ ps, const int* __restrict__ pd,
                                  const int* __restrict__ pq) {
    int count = g_ecount;
    int gw = (blockIdx.x * blockDim.x + threadIdx.x) >> 5;
    int lane = threadIdx.x & 31;
    int nw = (gridDim.x * blockDim.x) >> 5;
    int c = lane * 4;
    for (int i = gw; i < count; i += nw) {
        unsigned ent = g_elist[i];
        int e = (int)(ent & 0x3FFFFFFFu);
        unsigned f = ent >> 30;
        int src = __ldg(ps + e), dst = __ldg(pd + e);
        if (f & 1u) {   // dst needed: forward message
            int qid = __ldg(pq + e);
            float is = g_invs[src];
            float4 es = *(const float4*)(g_ek + (size_t)src * 128 + c);
            float4 qv = *(const float4*)(g_qe0 + (size_t)qid * 128 + c);
            float4 m = make_float4(es.x + qv.x * is, es.y + qv.y * is,
                                   es.z + qv.z * is, es.w + qv.w * is);
            red_add_v4(g_agg + (size_t)dst * 128 + c, m);
        }
        if (f & 2u) {   // src needed: reverse message
            float id = g_invs[dst];
            float4 ed = *(const float4*)(g_ek + (size_t)dst * 128 + c);
            float4 m2 = make_float4(ed.x * id, ed.y * id, ed.z * id, ed.w * id);
            red_add_v4(g_agg + (size_t)src * 128 + c, m2);
        }
    }
}

// ---------------- output: gather e = (e0 + agg*inv)/2 at users/items/negs ----------------
__global__ void output_kernel(const int* __restrict__ users, const int* __restrict__ items,
                              const int* __restrict__ negs, int B, float* __restrict__ out) {
    int g = blockIdx.x * blockDim.x + threadIdx.x;
    int idx = g >> 5, lane = g & 31;
    if (idx >= 3 * B) return;
    int part = idx / B, b = idx % B;
    int r = (part == 0) ? users[b] : ((part == 1) ? items[b] : negs[b]);
    int c = lane * 4;
    float inv = g_invs[r];
    float4 ev = *(const float4*)(g_ek + (size_t)r * 128 + c);
    float4 av = *(const float4*)(g_agg + (size_t)r * 128 + c);
    float4 v = make_float4((ev.x + av.x * inv) * 0.5f, (ev.y + av.y * inv) * 0.5f,
                           (ev.z + av.z * inv) * 0.5f, (ev.w + av.w * inv) * 0.5f);
    if (part == 0 && c >= 64) {
        float4 qb = *(const float4*)(g_qb + (size_t)b * 64 + (c - 64));
        v.x += qb.x; v.y += qb.y; v.z += qb.z; v.w += qb.w;
    }
    *(float4*)(out + (size_t)idx * 128 + c) = v;
}

// ---------------- launch ----------------
extern "C" void kernel_launch(void* const* d_in, const int* in_sizes, int n_in,
                              void* d_out, int out_size) {
    const float* W_word   = (const float*)d_in[0];
    const float* W_query  = (const float*)d_in[1];
    const float* W_entity = (const float*)d_in[2];
    const float* Wq       = (const float*)d_in[3];
    const float* Wk       = (const float*)d_in[4];
    const float* Wv       = (const float*)d_in[5];
    const float* Wo       = (const float*)d_in[6];
    const int* qids   = (const int*)d_in[7];
    const int* rids   = (const int*)d_in[8];
    const int* pdst   = (const int*)d_in[9];
    const int* p_src  = (const int*)d_in[10];
    const int* p_dst  = (const int*)d_in[11];
    const int* p_qid  = (const int*)d_in[12];
    const int* users  = (const int*)d_in[13];
    const int* items  = (const int*)d_in[14];
    const int* negs   = (const int*)d_in[15];
    const int* qwords = (const int*)d_in[16];

    int NW = in_sizes[0] / 64;
    int Q = in_sizes[1] / 64;
    int N = in_sizes[2] / 64;
    int R = in_sizes[9];
    int E = in_sizes[10];
    int B = in_sizes[13];

    zero_kernel<<<4096, 256>>>(N);
    precompute_P<<<64, 256>>>(Wv, Wo);
    mark_needed<<<(3 * B + 255) / 256, 256>>>(users, items, negs, B);

    {
        int smem = 98304 + 17408;   // 115712 B
        cudaFuncSetAttribute(fuse_zqk, cudaFuncAttributeMaxDynamicSharedMemorySize, smem);
        int ntiles = (NW + 31) / 32;
        fuse_zqk<<<ntiles < 592 ? ntiles : 592, 384, smem>>>(W_word, Wq, Wk, NW);
    }

    edge_scan_kernel<<<(E + 255) / 256, 256>>>(p_src, p_dst, E);

    attn_kernel<<<1184, 256>>>(qids, rids, qwords, Q, R, B);

    profile_kernel<<<(R * 16 + 255) / 256, 256>>>(pdst, R);
    build_kernel<<<(N * 32 + 255) / 256, 256>>>(W_query, W_entity, Q, N);

    edge_apply_kernel<<<1024, 256>>>(p_src, p_dst, p_qid);

    output_kernel<<<(3 * B * 32 + 255) / 256, 256>>>(users, items, negs, B, (float*)d_out);
}

// round 13
// speedup vs baseline: 1.5768x; 1.0793x over previous
#include <cuda_runtime.h>
#include <math.h>
#include <stdint.h>

// Problem dimensions (fixed dataset; runtime values still read from in_sizes)
#define WORD_N   50000
#define QUERY_N  50000
#define ENT_N    100000
#define REV_N    100000
#define EDGE_N   2000000
#define BATCH_N  1024
#define DWDIM    64
#define DDIM     128

typedef unsigned long long u64t;

// ---------------- scratch (static __device__, no allocation) ----------------
__device__ __align__(16) float g_hq[QUERY_N * DWDIM];
__device__ __align__(16) float g_hr[REV_N * DWDIM];
__device__ __align__(16) float g_qb[BATCH_N * DWDIM];
__device__ __align__(16) float g_enth[ENT_N * DWDIM];
__device__ __align__(16) float g_degp[ENT_N];
__device__ __align__(16) float g_degi[ENT_N];
__device__ __align__(16) float g_invs[ENT_N];
__device__ __align__(16) float g_ek[ENT_N * DDIM];
__device__ __align__(16) float g_qe0[QUERY_N * DDIM];
__device__ __align__(16) float g_agg[ENT_N * DDIM];
__device__ __align__(16) float g_P[4 * 64 * 64];        // P_h = Wv[:,h16] @ Wo[h16,:]
__device__ __align__(16) float g_QKW[WORD_N * 128];     // per word: [q(64) | k(64)]
__device__ __align__(16) float g_Z[WORD_N * 256];       // per word: [h0|h1|h2|h3] = x_w @ P_h
__device__ __align__(16) unsigned int g_bitmap[4096];   // needed-entity bitmap (100K bits)
__device__ int g_ecount;
__device__ __align__(16) unsigned int g_elist[EDGE_N];  // compact hit edges (flags in bits 30-31)

// ---------------- helpers ----------------
__device__ __forceinline__ u64t pack1(float x) {
    u64t r; asm("mov.b64 %0, {%1,%1};" : "=l"(r) : "f"(x)); return r;
}
__device__ __forceinline__ u64t ffma2(u64t a, u64t b, u64t c) {
    u64t d; asm("fma.rn.f32x2 %0, %1, %2, %3;" : "=l"(d) : "l"(a), "l"(b), "l"(c));
    return d;
}
__device__ __forceinline__ void red_add_v4(float* p, float4 v) {
    asm volatile("red.global.add.v4.f32 [%0], {%1,%2,%3,%4};"
                 :: "l"(p), "f"(v.x), "f"(v.y), "f"(v.z), "f"(v.w) : "memory");
}

// ---------------- zero scratch (agg handled separately by zero_needed) ----------------
__global__ void zero_kernel(int N) {
    int g = blockIdx.x * blockDim.x + threadIdx.x;
    int stride = gridDim.x * blockDim.x;
    float4 z = make_float4(0.f, 0.f, 0.f, 0.f);
    int n_eh4 = N * 16;
    for (int i = g; i < n_eh4; i += stride) ((float4*)g_enth)[i] = z;
    int n4 = N / 4;
    for (int i = g; i < n4; i += stride) { ((float4*)g_degp)[i] = z; ((float4*)g_degi)[i] = z; }
    if (g < 4096) g_bitmap[g] = 0u;
    if (g == 0) g_ecount = 0;
}

// ---------------- zero only the needed agg rows ----------------
__global__ void zero_needed(const int* __restrict__ users, const int* __restrict__ items,
                            const int* __restrict__ negs, int B) {
    int g = blockIdx.x * blockDim.x + threadIdx.x;
    int idx = g >> 5, lane = g & 31;
    if (idx >= 3 * B) return;
    int part = idx / B, b = idx % B;
    int r = (part == 0) ? users[b] : ((part == 1) ? items[b] : negs[b]);
    *(float4*)(g_agg + (size_t)r * 128 + lane * 4) = make_float4(0.f, 0.f, 0.f, 0.f);
}

// ---------------- precompute P_h = Wv[:, h*16:(h+1)*16] @ Wo[h*16:(h+1)*16, :] ----------------
__global__ void precompute_P(const float* __restrict__ Wv, const float* __restrict__ Wo) {
    int t = blockIdx.x * blockDim.x + threadIdx.x;
    if (t >= 4 * 64 * 64) return;
    int h = t >> 12, d = (t >> 6) & 63, c = t & 63;
    float s = 0.f;
    #pragma unroll
    for (int u = 0; u < 16; u++)
        s += Wv[d * 64 + h * 16 + u] * Wo[(h * 16 + u) * 64 + c];
    g_P[t] = s;
}

// ---------------- mark needed entities from users/items/negs ----------------
__global__ void mark_needed(const int* __restrict__ users, const int* __restrict__ items,
                            const int* __restrict__ negs, int B) {
    int g = blockIdx.x * blockDim.x + threadIdx.x;
    if (g >= 3 * B) return;
    int part = g / B, b = g % B;
    int r = (part == 0) ? users[b] : ((part == 1) ? items[b] : negs[b]);
    atomicOr(&g_bitmap[r >> 5], 1u << (r & 31));
}

// ---------------- fused Z + QK precompute v4b: column-split halves, 64-word tiles ----------------
// Block handles 192 cols (half of [P|Wq|Wk]) chosen by blockIdx parity: B tile 48KB.
// 64-word x tiles; thread owns 4 words x 2 quads -> 4 LDS.128 : 16 FFMA2 per d.
// WSTRIDE=66 keeps every ulonglong2 x-load 16B-aligned (66*8 = 528 = 16*33).
// smem 82944 B -> 2 CTAs/SM.
#define WSTRIDE 66
__global__ __launch_bounds__(384) void fuse_zqk(
    const float* __restrict__ W_word, const float* __restrict__ Wq,
    const float* __restrict__ Wk, int NW)
{
    extern __shared__ char sm[];
    float* sB = (float*)sm;                      // 64*192 floats = 49152 B
    u64t* sx2 = (u64t*)(sm + 49152);             // 64*WSTRIDE u64 = 33792 B
    int t = threadIdx.x;
    int colbase = (blockIdx.x & 1) * 192;

    for (int i = t; i < 12288; i += 384) {
        int d = i / 192, c = i % 192;
        int gc = colbase + c;
        float v;
        if (gc < 256)      v = g_P[((gc >> 6) << 12) + d * 64 + (gc & 63)];
        else if (gc < 320) v = Wq[d * 64 + (gc - 256)];
        else               v = Wk[d * 64 + (gc - 320)];
        sB[d * 192 + c] = v;
    }

    int tc = t % 24;            // quad-pair index within half
    int tw = t / 24;            // 16 word groups x 4 words
    int cA = tc * 4;            // local cols [0,96)
    int cB = 96 + tc * 4;       // local cols [96,192)
    int gcA = colbase + cA, gcB = colbase + cB;   // quads never straddle 256/320
    int ntiles = (NW + 63) / 64;
    int nstreams = gridDim.x >> 1;

    for (int tile = blockIdx.x >> 1; tile < ntiles; tile += nstreams) {
        __syncthreads();
        for (int i = t; i < 4096; i += 384) {
            int w = i >> 6, d = i & 63;
            int gw = tile * 64 + w;
            float v = W_word[(size_t)(gw < NW ? gw : 0) * 64 + d];
            sx2[d * WSTRIDE + w] = pack1(v);
        }
        __syncthreads();

        u64t acc[4][4];
        #pragma unroll
        for (int i = 0; i < 4; i++)
            #pragma unroll
            for (int p = 0; p < 4; p++) acc[i][p] = 0ULL;

        #pragma unroll 4
        for (int d = 0; d < 64; d++) {
            ulonglong2 bA = *(const ulonglong2*)(sB + d * 192 + cA);
            ulonglong2 bB = *(const ulonglong2*)(sB + d * 192 + cB);
            const u64t* xr = sx2 + d * WSTRIDE + tw * 4;
            ulonglong2 xa = *(const ulonglong2*)(xr);
            ulonglong2 xb = *(const ulonglong2*)(xr + 2);
            u64t xv[4] = {xa.x, xa.y, xb.x, xb.y};
            #pragma unroll
            for (int i = 0; i < 4; i++) {
                acc[i][0] = ffma2(xv[i], bA.x, acc[i][0]);
                acc[i][1] = ffma2(xv[i], bA.y, acc[i][1]);
                acc[i][2] = ffma2(xv[i], bB.x, acc[i][2]);
                acc[i][3] = ffma2(xv[i], bB.y, acc[i][3]);
            }
        }

        int wbase = tile * 64 + tw * 4;
        #pragma unroll
        for (int i = 0; i < 4; i++) {
            int w = wbase + i;
            if (w >= NW) break;
            float* oA;
            if (gcA < 256)      oA = g_Z + (size_t)w * 256 + gcA;
            else if (gcA < 320) oA = g_QKW + (size_t)w * 128 + (gcA - 256);
            else                oA = g_QKW + (size_t)w * 128 + 64 + (gcA - 320);
            *(ulonglong2*)oA = make_ulonglong2(acc[i][0], acc[i][1]);
            float* oB;
            if (gcB < 256)      oB = g_Z + (size_t)w * 256 + gcB;
            else if (gcB < 320) oB = g_QKW + (size_t)w * 128 + (gcB - 256);
            else                oB = g_QKW + (size_t)w * 128 + 64 + (gcB - 320);
            *(ulonglong2*)oB = make_ulonglong2(acc[i][2], acc[i][3]);
        }
    }
}

// ---------------- attention v3: padded smem-staged QK + Z-combine (unchanged) ----------------
#define QKROW 132     // 128 data floats + 4 pad -> conflict-free k-phase
__global__ __launch_bounds__(256)
void attn_kernel(const int* __restrict__ qids, const int* __restrict__ rids,
                 const int* __restrict__ bids, int Q, int R, int B)
{
    __shared__ float sqk[8][8 * QKROW];
    int tid = threadIdx.x, lane = tid & 31, warp = tid >> 5;
    float* sw = sqk[warp];
    int T = Q + R + B;
    int hh = lane >> 3, jj = lane & 7;
    int srow = lane >> 2, sseg = lane & 3;

    for (int doc = blockIdx.x * 8 + warp; doc < T; doc += gridDim.x * 8) {
        const int* ids; float* outp;
        if (doc < Q)          { ids = qids + (size_t)doc * 8;       outp = g_hq + (size_t)doc * 64; }
        else if (doc < Q + R) { int r = doc - Q; ids = rids + (size_t)r * 8; outp = g_hr + (size_t)r * 64; }
        else                  { int b = doc - Q - R; ids = bids + (size_t)b * 8; outp = g_qb + (size_t)b * 64; }

        int myid = ids[jj];

        {
            int rid = ids[srow];
            const float4* src = (const float4*)(g_QKW + (size_t)rid * 128);
            float4* dst = (float4*)(sw + srow * QKROW);
            #pragma unroll
            for (int p = 0; p < 4; p++) {
                dst[p * 8 + sseg * 2]     = __ldg(src + p * 8 + sseg * 2);
                dst[p * 8 + sseg * 2 + 1] = __ldg(src + p * 8 + sseg * 2 + 1);
            }
        }
        __syncwarp();

        const float4* kp = (const float4*)(sw + jj * QKROW + 64 + hh * 16);
        float4 k0 = kp[0], k1 = kp[1], k2 = kp[2], k3 = kp[3];

        float a_acc = 0.f;
        #pragma unroll
        for (int l = 0; l < 8; l++) {
            const float4* qp = (const float4*)(sw + l * QKROW + hh * 16);
            float4 q0 = qp[0], q1 = qp[1], q2 = qp[2], q3 = qp[3];
            float s = q0.x*k0.x + q0.y*k0.y + q0.z*k0.z + q0.w*k0.w
                    + q1.x*k1.x + q1.y*k1.y + q1.z*k1.z + q1.w*k1.w
                    + q2.x*k2.x + q2.y*k2.y + q2.z*k2.z + q2.w*k2.w
                    + q3.x*k3.x + q3.y*k3.y + q3.z*k3.z + q3.w*k3.w;
            float e = __expf(s * 0.25f);
            float t = e;
            t += __shfl_xor_sync(0xffffffffu, t, 1);
            t += __shfl_xor_sync(0xffffffffu, t, 2);
            t += __shfl_xor_sync(0xffffffffu, t, 4);
            a_acc += e * __frcp_rn(t);
        }
        a_acc *= 0.125f;

        int c0 = lane * 2;
        u64t o = 0;
        #pragma unroll
        for (int j = 0; j < 8; j++) {
            int idz = __shfl_sync(0xffffffffu, myid, j);
            const float* zr = g_Z + (size_t)idz * 256 + c0;
            #pragma unroll
            for (int h = 0; h < 4; h++) {
                float av = __shfl_sync(0xffffffffu, a_acc, h * 8 + j);
                o = ffma2(pack1(av), __ldg((const u64t*)(zr + h * 64)), o);
            }
        }
        *(u64t*)(outp + c0) = o;
        __syncwarp();
    }
}

// ---------------- profile aggregation: ent_h += h_review, deg_p += 1 ----------------
__global__ void profile_kernel(const int* __restrict__ pdst, int R) {
    int g = blockIdx.x * blockDim.x + threadIdx.x;
    int r = g >> 4, q = g & 15;
    if (r >= R) return;
    int d = pdst[r];
    float4 v = *(const float4*)(g_hr + (size_t)r * 64 + q * 4);
    red_add_v4(g_enth + (size_t)d * 64 + q * 4, v);
    if (q == 0) atomicAdd(g_degp + d, 1.0f);
}

// ---------------- edge scan: degi + bitmap test + compact hit list ----------------
__global__ void edge_scan_kernel(const int* __restrict__ ps, const int* __restrict__ pd, int E) {
    int e = blockIdx.x * blockDim.x + threadIdx.x;
    if (e >= E) return;
    int s = __ldg(ps + e), d = __ldg(pd + e);
    atomicAdd(g_degi + s, 1.0f);
    atomicAdd(g_degi + d, 1.0f);
    unsigned f = ((g_bitmap[d >> 5] >> (d & 31)) & 1u)
               | (((g_bitmap[s >> 5] >> (s & 31)) & 1u) << 1);
    if (f) {
        int idx = atomicAdd(&g_ecount, 1);
        g_elist[idx] = (unsigned)e | (f << 30);
    }
}

// ---------------- build e_0, q_e0, inv_sqrt ----------------
__global__ void build_kernel(const float* __restrict__ W_query,
                             const float* __restrict__ W_entity, int Q, int N) {
    int g = blockIdx.x * blockDim.x + threadIdx.x;
    int n = g >> 5, lane = g & 31;
    if (n >= N) return;
    int c = lane * 4;
    if (lane == 0) g_invs[n] = 1.0f / sqrtf(fmaxf(g_degi[n], 1.0f));
    float4 v;
    if (c < 64) {
        v = *(const float4*)(W_entity + (size_t)n * 64 + c);
    } else {
        float invdp = 1.0f / fmaxf(g_degp[n], 1.0f);
        float4 hv = *(const float4*)(g_enth + (size_t)n * 64 + (c - 64));
        v = make_float4(hv.x * invdp, hv.y * invdp, hv.z * invdp, hv.w * invdp);
    }
    *(float4*)(g_ek + (size_t)n * 128 + c) = v;
    if (n < Q) {
        float4 u;
        if (c < 64) u = *(const float4*)(W_query + (size_t)n * 64 + c);
        else        u = *(const float4*)(g_hq + (size_t)n * 64 + (c - 64));
        *(float4*)(g_qe0 + (size_t)n * 128 + c) = u;
    }
}

// ---------------- edge apply: warp per compact hit entry (grid-stride) ----------------
__global__ void edge_apply_kernel(const int* __restrict__ ps, const int* __restrict__ pd,
                                  const int* __restrict__ pq) {
    int count = g_ecount;
    int gw = (blockIdx.x * blockDim.x + threadIdx.x) >> 5;
    int lane = threadIdx.x & 31;
    int nw = (gridDim.x * blockDim.x) >> 5;
    int c = lane * 4;
    for (int i = gw; i < count; i += nw) {
        unsigned ent = g_elist[i];
        int e = (int)(ent & 0x3FFFFFFFu);
        unsigned f = ent >> 30;
        int src = __ldg(ps + e), dst = __ldg(pd + e);
        if (f & 1u) {
            int qid = __ldg(pq + e);
            float is = g_invs[src];
            float4 es = *(const float4*)(g_ek + (size_t)src * 128 + c);
            float4 qv = *(const float4*)(g_qe0 + (size_t)qid * 128 + c);
            float4 m = make_float4(es.x + qv.x * is, es.y + qv.y * is,
                                   es.z + qv.z * is, es.w + qv.w * is);
            red_add_v4(g_agg + (size_t)dst * 128 + c, m);
        }
        if (f & 2u) {
            float id = g_invs[dst];
            float4 ed = *(const float4*)(g_ek + (size_t)dst * 128 + c);
            float4 m2 = make_float4(ed.x * id, ed.y * id, ed.z * id, ed.w * id);
            red_add_v4(g_agg + (size_t)src * 128 + c, m2);
        }
    }
}

// ---------------- output: gather e = (e0 + agg*inv)/2 at users/items/negs ----------------
__global__ void output_kernel(const int* __restrict__ users, const int* __restrict__ items,
                              const int* __restrict__ negs, int B, float* __restrict__ out) {
    int g = blockIdx.x * blockDim.x + threadIdx.x;
    int idx = g >> 5, lane = g & 31;
    if (idx >= 3 * B) return;
    int part = idx / B, b = idx % B;
    int r = (part == 0) ? users[b] : ((part == 1) ? items[b] : negs[b]);
    int c = lane * 4;
    float inv = g_invs[r];
    float4 ev = *(const float4*)(g_ek + (size_t)r * 128 + c);
    float4 av = *(const float4*)(g_agg + (size_t)r * 128 + c);
    float4 v = make_float4((ev.x + av.x * inv) * 0.5f, (ev.y + av.y * inv) * 0.5f,
                           (ev.z + av.z * inv) * 0.5f, (ev.w + av.w * inv) * 0.5f);
    if (part == 0 && c >= 64) {
        float4 qb = *(const float4*)(g_qb + (size_t)b * 64 + (c - 64));
        v.x += qb.x; v.y += qb.y; v.z += qb.z; v.w += qb.w;
    }
    *(float4*)(out + (size_t)idx * 128 + c) = v;
}

// ---------------- launch ----------------
extern "C" void kernel_launch(void* const* d_in, const int* in_sizes, int n_in,
                              void* d_out, int out_size) {
    const float* W_word   = (const float*)d_in[0];
    const float* W_query  = (const float*)d_in[1];
    const float* W_entity = (const float*)d_in[2];
    const float* Wq       = (const float*)d_in[3];
    const float* Wk       = (const float*)d_in[4];
    const float* Wv       = (const float*)d_in[5];
    const float* Wo       = (const float*)d_in[6];
    const int* qids   = (const int*)d_in[7];
    const int* rids   = (const int*)d_in[8];
    const int* pdst   = (const int*)d_in[9];
    const int* p_src  = (const int*)d_in[10];
    const int* p_dst  = (const int*)d_in[11];
    const int* p_qid  = (const int*)d_in[12];
    const int* users  = (const int*)d_in[13];
    const int* items  = (const int*)d_in[14];
    const int* negs   = (const int*)d_in[15];
    const int* qwords = (const int*)d_in[16];

    int NW = in_sizes[0] / 64;
    int Q = in_sizes[1] / 64;
    int N = in_sizes[2] / 64;
    int R = in_sizes[9];
    int E = in_sizes[10];
    int B = in_sizes[13];

    zero_kernel<<<2048, 256>>>(N);
    precompute_P<<<64, 256>>>(Wv, Wo);
    mark_needed<<<(3 * B + 255) / 256, 256>>>(users, items, negs, B);
    zero_needed<<<(3 * B * 32 + 255) / 256, 256>>>(users, items, negs, B);

    {
        int smem = 49152 + 33792;   // 82944 B -> 2 CTAs/SM
        cudaFuncSetAttribute(fuse_zqk, cudaFuncAttributeMaxDynamicSharedMemorySize, smem);
        fuse_zqk<<<592, 384, smem>>>(W_word, Wq, Wk, NW);
    }

    edge_scan_kernel<<<(E + 255) / 256, 256>>>(p_src, p_dst, E);

    attn_kernel<<<1184, 256>>>(qids, rids, qwords, Q, R, B);

    profile_kernel<<<(R * 16 + 255) / 256, 256>>>(pdst, R);
    build_kernel<<<(N * 32 + 255) / 256, 256>>>(W_query, W_entity, Q, N);

    edge_apply_kernel<<<1024, 256>>>(p_src, p_dst, p_qid);

    output_kernel<<<(3 * B * 32 + 255) / 256, 256>>>(users, items, negs, B, (float*)d_out);
}

// round 14
// speedup vs baseline: 1.5967x; 1.0126x over previous
#include <cuda_runtime.h>
#include <math.h>
#include <stdint.h>

// Problem dimensions (fixed dataset; runtime values still read from in_sizes)
#define WORD_N   50000
#define QUERY_N  50000
#define ENT_N    100000
#define REV_N    100000
#define EDGE_N   2000000
#define BATCH_N  1024
#define DWDIM    64
#define DDIM     128

typedef unsigned long long u64t;

// ---------------- scratch (static __device__, no allocation) ----------------
__device__ __align__(16) float g_qb[BATCH_N * DWDIM];
__device__ __align__(16) float g_enth[ENT_N * DWDIM];
__device__ __align__(16) float g_degp[ENT_N];
__device__ __align__(16) float g_degi[ENT_N];
__device__ __align__(16) float g_invs[ENT_N];
__device__ __align__(16) float g_ek[ENT_N * DDIM];
__device__ __align__(16) float g_qe0[QUERY_N * DDIM];
__device__ __align__(16) float g_agg[ENT_N * DDIM];
__device__ __align__(16) float g_P[4 * 64 * 64];        // P_h = Wv[:,h16] @ Wo[h16,:]
__device__ __align__(16) float g_QKW[WORD_N * 128];     // per word: [q(64) | k(64)]
__device__ __align__(16) float g_Z[WORD_N * 256];       // per word: [h0|h1|h2|h3] = x_w @ P_h
__device__ __align__(16) unsigned int g_bitmap[4096];   // needed-entity bitmap (100K bits)
__device__ int g_ecount;
__device__ __align__(16) unsigned int g_elist[EDGE_N];  // compact hit edges (flags in bits 30-31)

// ---------------- helpers ----------------
__device__ __forceinline__ u64t pack1(float x) {
    u64t r; asm("mov.b64 %0, {%1,%1};" : "=l"(r) : "f"(x)); return r;
}
__device__ __forceinline__ u64t ffma2(u64t a, u64t b, u64t c) {
    u64t d; asm("fma.rn.f32x2 %0, %1, %2, %3;" : "=l"(d) : "l"(a), "l"(b), "l"(c));
    return d;
}
__device__ __forceinline__ void red_add_v4(float* p, float4 v) {
    asm volatile("red.global.add.v4.f32 [%0], {%1,%2,%3,%4};"
                 :: "l"(p), "f"(v.x), "f"(v.y), "f"(v.z), "f"(v.w) : "memory");
}
__device__ __forceinline__ void red_add_v2(float* p, float x, float y) {
    asm volatile("red.global.add.v2.f32 [%0], {%1,%2};"
                 :: "l"(p), "f"(x), "f"(y) : "memory");
}

// ---------------- zero scratch (agg handled separately by zero_needed) ----------------
__global__ void zero_kernel(int N) {
    int g = blockIdx.x * blockDim.x + threadIdx.x;
    int stride = gridDim.x * blockDim.x;
    float4 z = make_float4(0.f, 0.f, 0.f, 0.f);
    int n_eh4 = N * 16;
    for (int i = g; i < n_eh4; i += stride) ((float4*)g_enth)[i] = z;
    int n4 = N / 4;
    for (int i = g; i < n4; i += stride) { ((float4*)g_degp)[i] = z; ((float4*)g_degi)[i] = z; }
    if (g < 4096) g_bitmap[g] = 0u;
    if (g == 0) g_ecount = 0;
}

// ---------------- zero only the needed agg rows ----------------
__global__ void zero_needed(const int* __restrict__ users, const int* __restrict__ items,
                            const int* __restrict__ negs, int B) {
    int g = blockIdx.x * blockDim.x + threadIdx.x;
    int idx = g >> 5, lane = g & 31;
    if (idx >= 3 * B) return;
    int part = idx / B, b = idx % B;
    int r = (part == 0) ? users[b] : ((part == 1) ? items[b] : negs[b]);
    *(float4*)(g_agg + (size_t)r * 128 + lane * 4) = make_float4(0.f, 0.f, 0.f, 0.f);
}

// ---------------- precompute P_h = Wv[:, h*16:(h+1)*16] @ Wo[h*16:(h+1)*16, :] ----------------
__global__ void precompute_P(const float* __restrict__ Wv, const float* __restrict__ Wo) {
    int t = blockIdx.x * blockDim.x + threadIdx.x;
    if (t >= 4 * 64 * 64) return;
    int h = t >> 12, d = (t >> 6) & 63, c = t & 63;
    float s = 0.f;
    #pragma unroll
    for (int u = 0; u < 16; u++)
        s += Wv[d * 64 + h * 16 + u] * Wo[(h * 16 + u) * 64 + c];
    g_P[t] = s;
}

// ---------------- mark needed entities from users/items/negs ----------------
__global__ void mark_needed(const int* __restrict__ users, const int* __restrict__ items,
                            const int* __restrict__ negs, int B) {
    int g = blockIdx.x * blockDim.x + threadIdx.x;
    if (g >= 3 * B) return;
    int part = g / B, b = g % B;
    int r = (part == 0) ? users[b] : ((part == 1) ? items[b] : negs[b]);
    atomicOr(&g_bitmap[r >> 5], 1u << (r & 31));
}

// ---------------- fused Z + QK precompute v4b (unchanged from round 13) ----------------
#define WSTRIDE 66
__global__ __launch_bounds__(384) void fuse_zqk(
    const float* __restrict__ W_word, const float* __restrict__ Wq,
    const float* __restrict__ Wk, int NW)
{
    extern __shared__ char sm[];
    float* sB = (float*)sm;                      // 64*192 floats = 49152 B
    u64t* sx2 = (u64t*)(sm + 49152);             // 64*WSTRIDE u64 = 33792 B
    int t = threadIdx.x;
    int colbase = (blockIdx.x & 1) * 192;

    for (int i = t; i < 12288; i += 384) {
        int d = i / 192, c = i % 192;
        int gc = colbase + c;
        float v;
        if (gc < 256)      v = g_P[((gc >> 6) << 12) + d * 64 + (gc & 63)];
        else if (gc < 320) v = Wq[d * 64 + (gc - 256)];
        else               v = Wk[d * 64 + (gc - 320)];
        sB[d * 192 + c] = v;
    }

    int tc = t % 24;
    int tw = t / 24;
    int cA = tc * 4;
    int cB = 96 + tc * 4;
    int gcA = colbase + cA, gcB = colbase + cB;
    int ntiles = (NW + 63) / 64;
    int nstreams = gridDim.x >> 1;

    for (int tile = blockIdx.x >> 1; tile < ntiles; tile += nstreams) {
        __syncthreads();
        for (int i = t; i < 4096; i += 384) {
            int w = i >> 6, d = i & 63;
            int gw = tile * 64 + w;
            float v = W_word[(size_t)(gw < NW ? gw : 0) * 64 + d];
            sx2[d * WSTRIDE + w] = pack1(v);
        }
        __syncthreads();

        u64t acc[4][4];
        #pragma unroll
        for (int i = 0; i < 4; i++)
            #pragma unroll
            for (int p = 0; p < 4; p++) acc[i][p] = 0ULL;

        #pragma unroll 4
        for (int d = 0; d < 64; d++) {
            ulonglong2 bA = *(const ulonglong2*)(sB + d * 192 + cA);
            ulonglong2 bB = *(const ulonglong2*)(sB + d * 192 + cB);
            const u64t* xr = sx2 + d * WSTRIDE + tw * 4;
            ulonglong2 xa = *(const ulonglong2*)(xr);
            ulonglong2 xb = *(const ulonglong2*)(xr + 2);
            u64t xv[4] = {xa.x, xa.y, xb.x, xb.y};
            #pragma unroll
            for (int i = 0; i < 4; i++) {
                acc[i][0] = ffma2(xv[i], bA.x, acc[i][0]);
                acc[i][1] = ffma2(xv[i], bA.y, acc[i][1]);
                acc[i][2] = ffma2(xv[i], bB.x, acc[i][2]);
                acc[i][3] = ffma2(xv[i], bB.y, acc[i][3]);
            }
        }

        int wbase = tile * 64 + tw * 4;
        #pragma unroll
        for (int i = 0; i < 4; i++) {
            int w = wbase + i;
            if (w >= NW) break;
            float* oA;
            if (gcA < 256)      oA = g_Z + (size_t)w * 256 + gcA;
            else if (gcA < 320) oA = g_QKW + (size_t)w * 128 + (gcA - 256);
            else                oA = g_QKW + (size_t)w * 128 + 64 + (gcA - 320);
            *(ulonglong2*)oA = make_ulonglong2(acc[i][0], acc[i][1]);
            float* oB;
            if (gcB < 256)      oB = g_Z + (size_t)w * 256 + gcB;
            else if (gcB < 320) oB = g_QKW + (size_t)w * 128 + (gcB - 256);
            else                oB = g_QKW + (size_t)w * 128 + 64 + (gcB - 320);
            *(ulonglong2*)oB = make_ulonglong2(acc[i][2], acc[i][3]);
        }
    }
}

// ---------------- attention v4: fused epilogue ----------------
// review docs -> RED into g_enth[pdst[r]] (+degp); query docs -> g_qe0 hi half;
// batch docs -> g_qb. g_hq/g_hr eliminated.
#define QKROW 132     // 128 data floats + 4 pad -> conflict-free k-phase
__global__ __launch_bounds__(256)
void attn_kernel(const int* __restrict__ qids, const int* __restrict__ rids,
                 const int* __restrict__ bids, const int* __restrict__ pdst,
                 int Q, int R, int B)
{
    __shared__ float sqk[8][8 * QKROW];
    int tid = threadIdx.x, lane = tid & 31, warp = tid >> 5;
    float* sw = sqk[warp];
    int T = Q + R + B;
    int hh = lane >> 3, jj = lane & 7;
    int srow = lane >> 2, sseg = lane & 3;

    for (int doc = blockIdx.x * 8 + warp; doc < T; doc += gridDim.x * 8) {
        const int* ids;
        if (doc < Q)          ids = qids + (size_t)doc * 8;
        else if (doc < Q + R) ids = rids + (size_t)(doc - Q) * 8;
        else                  ids = bids + (size_t)(doc - Q - R) * 8;

        int myid = ids[jj];

        {
            int rid = ids[srow];
            const float4* src = (const float4*)(g_QKW + (size_t)rid * 128);
            float4* dst = (float4*)(sw + srow * QKROW);
            #pragma unroll
            for (int p = 0; p < 4; p++) {
                dst[p * 8 + sseg * 2]     = __ldg(src + p * 8 + sseg * 2);
                dst[p * 8 + sseg * 2 + 1] = __ldg(src + p * 8 + sseg * 2 + 1);
            }
        }
        __syncwarp();

        const float4* kp = (const float4*)(sw + jj * QKROW + 64 + hh * 16);
        float4 k0 = kp[0], k1 = kp[1], k2 = kp[2], k3 = kp[3];

        float a_acc = 0.f;
        #pragma unroll
        for (int l = 0; l < 8; l++) {
            const float4* qp = (const float4*)(sw + l * QKROW + hh * 16);
            float4 q0 = qp[0], q1 = qp[1], q2 = qp[2], q3 = qp[3];
            float s = q0.x*k0.x + q0.y*k0.y + q0.z*k0.z + q0.w*k0.w
                    + q1.x*k1.x + q1.y*k1.y + q1.z*k1.z + q1.w*k1.w
                    + q2.x*k2.x + q2.y*k2.y + q2.z*k2.z + q2.w*k2.w
                    + q3.x*k3.x + q3.y*k3.y + q3.z*k3.z + q3.w*k3.w;
            float e = __expf(s * 0.25f);
            float t = e;
            t += __shfl_xor_sync(0xffffffffu, t, 1);
            t += __shfl_xor_sync(0xffffffffu, t, 2);
            t += __shfl_xor_sync(0xffffffffu, t, 4);
            a_acc += e * __frcp_rn(t);
        }
        a_acc *= 0.125f;

        int c0 = lane * 2;
        u64t o = 0;
        #pragma unroll
        for (int j = 0; j < 8; j++) {
            int idz = __shfl_sync(0xffffffffu, myid, j);
            const float* zr = g_Z + (size_t)idz * 256 + c0;
            #pragma unroll
            for (int h = 0; h < 4; h++) {
                float av = __shfl_sync(0xffffffffu, a_acc, h * 8 + j);
                o = ffma2(pack1(av), __ldg((const u64t*)(zr + h * 64)), o);
            }
        }

        // fused epilogue
        float2 ov = *(float2*)&o;
        if (doc < Q) {
            *(u64t*)(g_qe0 + (size_t)doc * 128 + 64 + c0) = o;
        } else if (doc < Q + R) {
            int r = doc - Q;
            int d = __ldg(pdst + r);
            red_add_v2(g_enth + (size_t)d * 64 + c0, ov.x, ov.y);
            if (lane == 0) atomicAdd(g_degp + d, 1.0f);
        } else {
            *(u64t*)(g_qb + (size_t)(doc - Q - R) * 64 + c0) = o;
        }
        __syncwarp();
    }
}

// ---------------- edge scan: degi + bitmap test + compact hit list ----------------
__global__ void edge_scan_kernel(const int* __restrict__ ps, const int* __restrict__ pd, int E) {
    int e = blockIdx.x * blockDim.x + threadIdx.x;
    if (e >= E) return;
    int s = __ldg(ps + e), d = __ldg(pd + e);
    atomicAdd(g_degi + s, 1.0f);
    atomicAdd(g_degi + d, 1.0f);
    unsigned f = ((g_bitmap[d >> 5] >> (d & 31)) & 1u)
               | (((g_bitmap[s >> 5] >> (s & 31)) & 1u) << 1);
    if (f) {
        int idx = atomicAdd(&g_ecount, 1);
        g_elist[idx] = (unsigned)e | (f << 30);
    }
}

// ---------------- build e_0, q_e0 lo half, inv_sqrt ----------------
__global__ void build_kernel(const float* __restrict__ W_query,
                             const float* __restrict__ W_entity, int Q, int N) {
    int g = blockIdx.x * blockDim.x + threadIdx.x;
    int n = g >> 5, lane = g & 31;
    if (n >= N) return;
    int c = lane * 4;
    if (lane == 0) g_invs[n] = 1.0f / sqrtf(fmaxf(g_degi[n], 1.0f));
    float4 v;
    if (c < 64) {
        v = *(const float4*)(W_entity + (size_t)n * 64 + c);
    } else {
        float invdp = 1.0f / fmaxf(g_degp[n], 1.0f);
        float4 hv = *(const float4*)(g_enth + (size_t)n * 64 + (c - 64));
        v = make_float4(hv.x * invdp, hv.y * invdp, hv.z * invdp, hv.w * invdp);
    }
    *(float4*)(g_ek + (size_t)n * 128 + c) = v;
    if (n < Q && c < 64) {
        // hi half (cols 64-127) already written by attn_kernel
        *(float4*)(g_qe0 + (size_t)n * 128 + c) =
            *(const float4*)(W_query + (size_t)n * 64 + c);
    }
}

// ---------------- edge apply: warp per compact hit entry (grid-stride) ----------------
__global__ void edge_apply_kernel(const int* __restrict__ ps, const int* __restrict__ pd,
                                  const int* __restrict__ pq) {
    int count = g_ecount;
    int gw = (blockIdx.x * blockDim.x + threadIdx.x) >> 5;
    int lane = threadIdx.x & 31;
    int nw = (gridDim.x * blockDim.x) >> 5;
    int c = lane * 4;
    for (int i = gw; i < count; i += nw) {
        unsigned ent = g_elist[i];
        int e = (int)(ent & 0x3FFFFFFFu);
        unsigned f = ent >> 30;
        int src = __ldg(ps + e), dst = __ldg(pd + e);
        if (f & 1u) {
            int qid = __ldg(pq + e);
            float is = g_invs[src];
            float4 es = *(const float4*)(g_ek + (size_t)src * 128 + c);
            float4 qv = *(const float4*)(g_qe0 + (size_t)qid * 128 + c);
            float4 m = make_float4(es.x + qv.x * is, es.y + qv.y * is,
                                   es.z + qv.z * is, es.w + qv.w * is);
            red_add_v4(g_agg + (size_t)dst * 128 + c, m);
        }
        if (f & 2u) {
            float id = g_invs[dst];
            float4 ed = *(const float4*)(g_ek + (size_t)dst * 128 + c);
            float4 m2 = make_float4(ed.x * id, ed.y * id, ed.z * id, ed.w * id);
            red_add_v4(g_agg + (size_t)src * 128 + c, m2);
        }
    }
}

// ---------------- output: gather e = (e0 + agg*inv)/2 at users/items/negs ----------------
__global__ void output_kernel(const int* __restrict__ users, const int* __restrict__ items,
                              const int* __restrict__ negs, int B, float* __restrict__ out) {
    int g = blockIdx.x * blockDim.x + threadIdx.x;
    int idx = g >> 5, lane = g & 31;
    if (idx >= 3 * B) return;
    int part = idx / B, b = idx % B;
    int r = (part == 0) ? users[b] : ((part == 1) ? items[b] : negs[b]);
    int c = lane * 4;
    float inv = g_invs[r];
    float4 ev = *(const float4*)(g_ek + (size_t)r * 128 + c);
    float4 av = *(const float4*)(g_agg + (size_t)r * 128 + c);
    float4 v = make_float4((ev.x + av.x * inv) * 0.5f, (ev.y + av.y * inv) * 0.5f,
                           (ev.z + av.z * inv) * 0.5f, (ev.w + av.w * inv) * 0.5f);
    if (part == 0 && c >= 64) {
        float4 qb = *(const float4*)(g_qb + (size_t)b * 64 + (c - 64));
        v.x += qb.x; v.y += qb.y; v.z += qb.z; v.w += qb.w;
    }
    *(float4*)(out + (size_t)idx * 128 + c) = v;
}

// ---------------- launch ----------------
extern "C" void kernel_launch(void* const* d_in, const int* in_sizes, int n_in,
                              void* d_out, int out_size) {
    const float* W_word   = (const float*)d_in[0];
    const float* W_query  = (const float*)d_in[1];
    const float* W_entity = (const float*)d_in[2];
    const float* Wq       = (const float*)d_in[3];
    const float* Wk       = (const float*)d_in[4];
    const float* Wv       = (const float*)d_in[5];
    const float* Wo       = (const float*)d_in[6];
    const int* qids   = (const int*)d_in[7];
    const int* rids   = (const int*)d_in[8];
    const int* pdst   = (const int*)d_in[9];
    const int* p_src  = (const int*)d_in[10];
    const int* p_dst  = (const int*)d_in[11];
    const int* p_qid  = (const int*)d_in[12];
    const int* users  = (const int*)d_in[13];
    const int* items  = (const int*)d_in[14];
    const int* negs   = (const int*)d_in[15];
    const int* qwords = (const int*)d_in[16];

    int NW = in_sizes[0] / 64;
    int Q = in_sizes[1] / 64;
    int N = in_sizes[2] / 64;
    int R = in_sizes[9];
    int E = in_sizes[10];
    int B = in_sizes[13];

    zero_kernel<<<2048, 256>>>(N);
    precompute_P<<<64, 256>>>(Wv, Wo);
    mark_needed<<<(3 * B + 255) / 256, 256>>>(users, items, negs, B);
    zero_needed<<<(3 * B * 32 + 255) / 256, 256>>>(users, items, negs, B);

    {
        int smem = 49152 + 33792;   // 82944 B -> 2 CTAs/SM
        cudaFuncSetAttribute(fuse_zqk, cudaFuncAttributeMaxDynamicSharedMemorySize, smem);
        fuse_zqk<<<592, 384, smem>>>(W_word, Wq, Wk, NW);
    }

    edge_scan_kernel<<<(E + 255) / 256, 256>>>(p_src, p_dst, E);

    attn_kernel<<<1184, 256>>>(qids, rids, qwords, pdst, Q, R, B);

    build_kernel<<<(N * 32 + 255) / 256, 256>>>(W_query, W_entity, Q, N);

    edge_apply_kernel<<<1024, 256>>>(p_src, p_dst, p_qid);

    output_kernel<<<(3 * B * 32 + 255) / 256, 256>>>(users, items, negs, B, (float*)d_out);
}

// round 16
// speedup vs baseline: 1.7138x; 1.0733x over previous
#include <cuda_runtime.h>
#include <cuda_bf16.h>
#include <math.h>
#include <stdint.h>

// Problem dimensions (fixed dataset; runtime values still read from in_sizes)
#define WORD_N   50000
#define QUERY_N  50000
#define ENT_N    100000
#define REV_N    100000
#define EDGE_N   2000000
#define BATCH_N  1024
#define DWDIM    64
#define DDIM     128

typedef unsigned long long u64t;

// ---------------- scratch (static __device__, no allocation) ----------------
__device__ __align__(16) float g_qb[BATCH_N * DWDIM];
__device__ __align__(16) float g_enth[ENT_N * DWDIM];
__device__ __align__(16) float g_degp[ENT_N];
__device__ __align__(16) float g_degi[ENT_N];
__device__ __align__(16) float g_invs[ENT_N];
__device__ __align__(16) float g_ek[ENT_N * DDIM];
__device__ __align__(16) float g_qe0[QUERY_N * DDIM];
__device__ __align__(16) float g_agg[ENT_N * DDIM];
__device__ __align__(16) float g_P[4 * 64 * 64];            // P_h = Wv[:,h16] @ Wo[h16,:]
__device__ __align__(16) float g_QKW[WORD_N * 128];         // per word: [q(64) | k(64)] fp32
__device__ __align__(16) __nv_bfloat16 g_Z[WORD_N * 256];   // per word: [h0|h1|h2|h3] bf16
__device__ __align__(16) unsigned int g_bitmap[4096];       // needed-entity bitmap
__device__ int g_ecount;
__device__ __align__(16) unsigned int g_elist[EDGE_N];      // compact hit edges (flags bits 30-31)

// ---------------- helpers ----------------
__device__ __forceinline__ u64t pack1(float x) {
    u64t r; asm("mov.b64 %0, {%1,%1};" : "=l"(r) : "f"(x)); return r;
}
__device__ __forceinline__ u64t ffma2(u64t a, u64t b, u64t c) {
    u64t d; asm("fma.rn.f32x2 %0, %1, %2, %3;" : "=l"(d) : "l"(a), "l"(b), "l"(c));
    return d;
}
__device__ __forceinline__ void red_add_v4(float* p, float4 v) {
    asm volatile("red.global.add.v4.f32 [%0], {%1,%2,%3,%4};"
                 :: "l"(p), "f"(v.x), "f"(v.y), "f"(v.z), "f"(v.w) : "memory");
}
__device__ __forceinline__ void red_add_v2(float* p, float x, float y) {
    asm volatile("red.global.add.v2.f32 [%0], {%1,%2};"
                 :: "l"(p), "f"(x), "f"(y) : "memory");
}
__device__ __forceinline__ unsigned bf2bits(__nv_bfloat162 h) {
    return *(unsigned*)&h;
}

// ---------------- zero scratch ----------------
__global__ void zero_kernel(int N) {
    int g = blockIdx.x * blockDim.x + threadIdx.x;
    int stride = gridDim.x * blockDim.x;
    float4 z = make_float4(0.f, 0.f, 0.f, 0.f);
    int n_eh4 = N * 16;
    for (int i = g; i < n_eh4; i += stride) ((float4*)g_enth)[i] = z;
    int n4 = N / 4;
    for (int i = g; i < n4; i += stride) { ((float4*)g_degp)[i] = z; ((float4*)g_degi)[i] = z; }
    if (g < 4096) g_bitmap[g] = 0u;
    if (g == 0) g_ecount = 0;
}

// ---------------- mark needed entities + zero their agg rows (merged) ----------------
__global__ void prep_needed(const int* __restrict__ users, const int* __restrict__ items,
                            const int* __restrict__ negs, int B) {
    int g = blockIdx.x * blockDim.x + threadIdx.x;
    int idx = g >> 5, lane = g & 31;
    if (idx >= 3 * B) return;
    int part = idx / B, b = idx % B;
    int r = (part == 0) ? users[b] : ((part == 1) ? items[b] : negs[b]);
    if (lane == 0) atomicOr(&g_bitmap[r >> 5], 1u << (r & 31));
    *(float4*)(g_agg + (size_t)r * 128 + lane * 4) = make_float4(0.f, 0.f, 0.f, 0.f);
}

// ---------------- precompute P_h = Wv[:, h*16:(h+1)*16] @ Wo[h*16:(h+1)*16, :] ----------------
__global__ void precompute_P(const float* __restrict__ Wv, const float* __restrict__ Wo) {
    int t = blockIdx.x * blockDim.x + threadIdx.x;
    if (t >= 4 * 64 * 64) return;
    int h = t >> 12, d = (t >> 6) & 63, c = t & 63;
    float s = 0.f;
    #pragma unroll
    for (int u = 0; u < 16; u++)
        s += Wv[d * 64 + h * 16 + u] * Wo[(h * 16 + u) * 64 + c];
    g_P[t] = s;
}

// ---------------- fused Z + QK precompute v5b: Z bf16, FULL region dispatch on BOTH quads ----------------
#define WSTRIDE 66
__global__ __launch_bounds__(384) void fuse_zqk(
    const float* __restrict__ W_word, const float* __restrict__ Wq,
    const float* __restrict__ Wk, int NW)
{
    extern __shared__ char sm[];
    float* sB = (float*)sm;                      // 64*192 floats = 49152 B
    u64t* sx2 = (u64t*)(sm + 49152);             // 64*WSTRIDE u64 = 33792 B
    int t = threadIdx.x;
    int colbase = (blockIdx.x & 1) * 192;

    for (int i = t; i < 12288; i += 384) {
        int d = i / 192, c = i % 192;
        int gc = colbase + c;
        float v;
        if (gc < 256)      v = g_P[((gc >> 6) << 12) + d * 64 + (gc & 63)];
        else if (gc < 320) v = Wq[d * 64 + (gc - 256)];
        else               v = Wk[d * 64 + (gc - 320)];
        sB[d * 192 + c] = v;
    }

    int tc = t % 24;
    int tw = t / 24;
    int cA = tc * 4;
    int cB = 96 + tc * 4;
    int gcA = colbase + cA, gcB = colbase + cB;   // quads never straddle 256/320
    int ntiles = (NW + 63) / 64;
    int nstreams = gridDim.x >> 1;

    for (int tile = blockIdx.x >> 1; tile < ntiles; tile += nstreams) {
        __syncthreads();
        for (int i = t; i < 4096; i += 384) {
            int w = i >> 6, d = i & 63;
            int gw = tile * 64 + w;
            float v = W_word[(size_t)(gw < NW ? gw : 0) * 64 + d];
            sx2[d * WSTRIDE + w] = pack1(v);
        }
        __syncthreads();

        u64t acc[4][4];
        #pragma unroll
        for (int i = 0; i < 4; i++)
            #pragma unroll
            for (int p = 0; p < 4; p++) acc[i][p] = 0ULL;

        #pragma unroll 4
        for (int d = 0; d < 64; d++) {
            ulonglong2 bA = *(const ulonglong2*)(sB + d * 192 + cA);
            ulonglong2 bB = *(const ulonglong2*)(sB + d * 192 + cB);
            const u64t* xr = sx2 + d * WSTRIDE + tw * 4;
            ulonglong2 xa = *(const ulonglong2*)(xr);
            ulonglong2 xb = *(const ulonglong2*)(xr + 2);
            u64t xv[4] = {xa.x, xa.y, xb.x, xb.y};
            #pragma unroll
            for (int i = 0; i < 4; i++) {
                acc[i][0] = ffma2(xv[i], bA.x, acc[i][0]);
                acc[i][1] = ffma2(xv[i], bA.y, acc[i][1]);
                acc[i][2] = ffma2(xv[i], bB.x, acc[i][2]);
                acc[i][3] = ffma2(xv[i], bB.y, acc[i][3]);
            }
        }

        int wbase = tile * 64 + tw * 4;
        #pragma unroll
        for (int i = 0; i < 4; i++) {
            int w = wbase + i;
            if (w >= NW) break;
            // quad A: region dispatch (gcA in [0,96) u [192,288) across the two halves)
            if (gcA < 256) {
                float2 p0 = *(float2*)&acc[i][0];
                float2 p1 = *(float2*)&acc[i][1];
                uint2 st = make_uint2(bf2bits(__floats2bfloat162_rn(p0.x, p0.y)),
                                      bf2bits(__floats2bfloat162_rn(p1.x, p1.y)));
                *(uint2*)(g_Z + (size_t)w * 256 + gcA) = st;
            } else {
                float* oA;
                if (gcA < 320) oA = g_QKW + (size_t)w * 128 + (gcA - 256);
                else           oA = g_QKW + (size_t)w * 128 + 64 + (gcA - 320);
                *(ulonglong2*)oA = make_ulonglong2(acc[i][0], acc[i][1]);
            }
            // quad B: region dispatch (gcB in [96,192) u [288,384))
            if (gcB < 256) {
                float2 p0 = *(float2*)&acc[i][2];
                float2 p1 = *(float2*)&acc[i][3];
                uint2 st = make_uint2(bf2bits(__floats2bfloat162_rn(p0.x, p0.y)),
                                      bf2bits(__floats2bfloat162_rn(p1.x, p1.y)));
                *(uint2*)(g_Z + (size_t)w * 256 + gcB) = st;
            } else {
                float* oB;
                if (gcB < 320) oB = g_QKW + (size_t)w * 128 + (gcB - 256);
                else           oB = g_QKW + (size_t)w * 128 + 64 + (gcB - 320);
                *(ulonglong2*)oB = make_ulonglong2(acc[i][2], acc[i][3]);
            }
        }
    }
}

// ---------------- attention v5: fused epilogue + bf16 Z gather ----------------
#define QKROW 132
__global__ __launch_bounds__(256)
void attn_kernel(const int* __restrict__ qids, const int* __restrict__ rids,
                 const int* __restrict__ bids, const int* __restrict__ pdst,
                 int Q, int R, int B)
{
    __shared__ float sqk[8][8 * QKROW];
    int tid = threadIdx.x, lane = tid & 31, warp = tid >> 5;
    float* sw = sqk[warp];
    int T = Q + R + B;
    int hh = lane >> 3, jj = lane & 7;
    int srow = lane >> 2, sseg = lane & 3;

    for (int doc = blockIdx.x * 8 + warp; doc < T; doc += gridDim.x * 8) {
        const int* ids;
        if (doc < Q)          ids = qids + (size_t)doc * 8;
        else if (doc < Q + R) ids = rids + (size_t)(doc - Q) * 8;
        else                  ids = bids + (size_t)(doc - Q - R) * 8;

        int myid = ids[jj];

        {
            int rid = ids[srow];
            const float4* src = (const float4*)(g_QKW + (size_t)rid * 128);
            float4* dst = (float4*)(sw + srow * QKROW);
            #pragma unroll
            for (int p = 0; p < 4; p++) {
                dst[p * 8 + sseg * 2]     = __ldg(src + p * 8 + sseg * 2);
                dst[p * 8 + sseg * 2 + 1] = __ldg(src + p * 8 + sseg * 2 + 1);
            }
        }
        __syncwarp();

        const float4* kp = (const float4*)(sw + jj * QKROW + 64 + hh * 16);
        float4 k0 = kp[0], k1 = kp[1], k2 = kp[2], k3 = kp[3];

        float a_acc = 0.f;
        #pragma unroll
        for (int l = 0; l < 8; l++) {
            const float4* qp = (const float4*)(sw + l * QKROW + hh * 16);
            float4 q0 = qp[0], q1 = qp[1], q2 = qp[2], q3 = qp[3];
            float s = q0.x*k0.x + q0.y*k0.y + q0.z*k0.z + q0.w*k0.w
                    + q1.x*k1.x + q1.y*k1.y + q1.z*k1.z + q1.w*k1.w
                    + q2.x*k2.x + q2.y*k2.y + q2.z*k2.z + q2.w*k2.w
                    + q3.x*k3.x + q3.y*k3.y + q3.z*k3.z + q3.w*k3.w;
            float e = __expf(s * 0.25f);
            float t = e;
            t += __shfl_xor_sync(0xffffffffu, t, 1);
            t += __shfl_xor_sync(0xffffffffu, t, 2);
            t += __shfl_xor_sync(0xffffffffu, t, 4);
            a_acc += e * __frcp_rn(t);
        }
        a_acc *= 0.125f;

        int c0 = lane * 2;
        float o0 = 0.f, o1 = 0.f;
        #pragma unroll
        for (int j = 0; j < 8; j++) {
            int idz = __shfl_sync(0xffffffffu, myid, j);
            const unsigned* zr = (const unsigned*)(g_Z + (size_t)idz * 256 + c0);
            #pragma unroll
            for (int h = 0; h < 4; h++) {
                float av = __shfl_sync(0xffffffffu, a_acc, h * 8 + j);
                unsigned w = __ldg(zr + h * 32);   // +32 uints = 64 bf16 = one head block
                o0 = fmaf(av, __uint_as_float(w << 16), o0);           // bf16->f32 exact
                o1 = fmaf(av, __uint_as_float(w & 0xFFFF0000u), o1);
            }
        }

        // fused epilogue
        if (doc < Q) {
            *(float2*)(g_qe0 + (size_t)doc * 128 + 64 + c0) = make_float2(o0, o1);
        } else if (doc < Q + R) {
            int r = doc - Q;
            int d = __ldg(pdst + r);
            red_add_v2(g_enth + (size_t)d * 64 + c0, o0, o1);
            if (lane == 0) atomicAdd(g_degp + d, 1.0f);
        } else {
            *(float2*)(g_qb + (size_t)(doc - Q - R) * 64 + c0) = make_float2(o0, o1);
        }
        __syncwarp();
    }
}

// ---------------- edge scan: degi + bitmap test + compact hit list ----------------
__global__ void edge_scan_kernel(const int* __restrict__ ps, const int* __restrict__ pd, int E) {
    int e = blockIdx.x * blockDim.x + threadIdx.x;
    if (e >= E) return;
    int s = __ldg(ps + e), d = __ldg(pd + e);
    atomicAdd(g_degi + s, 1.0f);
    atomicAdd(g_degi + d, 1.0f);
    unsigned f = ((g_bitmap[d >> 5] >> (d & 31)) & 1u)
               | (((g_bitmap[s >> 5] >> (s & 31)) & 1u) << 1);
    if (f) {
        int idx = atomicAdd(&g_ecount, 1);
        g_elist[idx] = (unsigned)e | (f << 30);
    }
}

// ---------------- build e_0, q_e0 lo half, inv_sqrt ----------------
__global__ void build_kernel(const float* __restrict__ W_query,
                             const float* __restrict__ W_entity, int Q, int N) {
    int g = blockIdx.x * blockDim.x + threadIdx.x;
    int n = g >> 5, lane = g & 31;
    if (n >= N) return;
    int c = lane * 4;
    if (lane == 0) g_invs[n] = 1.0f / sqrtf(fmaxf(g_degi[n], 1.0f));
    float4 v;
    if (c < 64) {
        v = *(const float4*)(W_entity + (size_t)n * 64 + c);
    } else {
        float invdp = 1.0f / fmaxf(g_degp[n], 1.0f);
        float4 hv = *(const float4*)(g_enth + (size_t)n * 64 + (c - 64));
        v = make_float4(hv.x * invdp, hv.y * invdp, hv.z * invdp, hv.w * invdp);
    }
    *(float4*)(g_ek + (size_t)n * 128 + c) = v;
    if (n < Q && c < 64) {
        *(float4*)(g_qe0 + (size_t)n * 128 + c) =
            *(const float4*)(W_query + (size_t)n * 64 + c);
    }
}

// ---------------- edge apply: warp per compact hit entry (grid-stride) ----------------
__global__ void edge_apply_kernel(const int* __restrict__ ps, const int* __restrict__ pd,
                                  const int* __restrict__ pq) {
    int count = g_ecount;
    int gw = (blockIdx.x * blockDim.x + threadIdx.x) >> 5;
    int lane = threadIdx.x & 31;
    int nw = (gridDim.x * blockDim.x) >> 5;
    int c = lane * 4;
    for (int i = gw; i < count; i += nw) {
        unsigned ent = g_elist[i];
        int e = (int)(ent & 0x3FFFFFFFu);
        unsigned f = ent >> 30;
        int src = __ldg(ps + e), dst = __ldg(pd + e);
        if (f & 1u) {
            int qid = __ldg(pq + e);
            float is = g_invs[src];
            float4 es = *(const float4*)(g_ek + (size_t)src * 128 + c);
            float4 qv = *(const float4*)(g_qe0 + (size_t)qid * 128 + c);
            float4 m = make_float4(es.x + qv.x * is, es.y + qv.y * is,
                                   es.z + qv.z * is, es.w + qv.w * is);
            red_add_v4(g_agg + (size_t)dst * 128 + c, m);
        }
        if (f & 2u) {
            float id = g_invs[dst];
            float4 ed = *(const float4*)(g_ek + (size_t)dst * 128 + c);
            float4 m2 = make_float4(ed.x * id, ed.y * id, ed.z * id, ed.w * id);
            red_add_v4(g_agg + (size_t)src * 128 + c, m2);
        }
    }
}

// ---------------- output: gather e = (e0 + agg*inv)/2 at users/items/negs ----------------
__global__ void output_kernel(const int* __restrict__ users, const int* __restrict__ items,
                              const int* __restrict__ negs, int B, float* __restrict__ out) {
    int g = blockIdx.x * blockDim.x + threadIdx.x;
    int idx = g >> 5, lane = g & 31;
    if (idx >= 3 * B) return;
    int part = idx / B, b = idx % B;
    int r = (part == 0) ? users[b] : ((part == 1) ? items[b] : negs[b]);
    int c = lane * 4;
    float inv = g_invs[r];
    float4 ev = *(const float4*)(g_ek + (size_t)r * 128 + c);
    float4 av = *(const float4*)(g_agg + (size_t)r * 128 + c);
    float4 v = make_float4((ev.x + av.x * inv) * 0.5f, (ev.y + av.y * inv) * 0.5f,
                           (ev.z + av.z * inv) * 0.5f, (ev.w + av.w * inv) * 0.5f);
    if (part == 0 && c >= 64) {
        float4 qb = *(const float4*)(g_qb + (size_t)b * 64 + (c - 64));
        v.x += qb.x; v.y += qb.y; v.z += qb.z; v.w += qb.w;
    }
    *(float4*)(out + (size_t)idx * 128 + c) = v;
}

// ---------------- launch ----------------
extern "C" void kernel_launch(void* const* d_in, const int* in_sizes, int n_in,
                              void* d_out, int out_size) {
    const float* W_word   = (const float*)d_in[0];
    const float* W_query  = (const float*)d_in[1];
    const float* W_entity = (const float*)d_in[2];
    const float* Wq       = (const float*)d_in[3];
    const float* Wk       = (const float*)d_in[4];
    const float* Wv       = (const float*)d_in[5];
    const float* Wo       = (const float*)d_in[6];
    const int* qids   = (const int*)d_in[7];
    const int* rids   = (const int*)d_in[8];
    const int* pdst   = (const int*)d_in[9];
    const int* p_src  = (const int*)d_in[10];
    const int* p_dst  = (const int*)d_in[11];
    const int* p_qid  = (const int*)d_in[12];
    const int* users  = (const int*)d_in[13];
    const int* items  = (const int*)d_in[14];
    const int* negs   = (const int*)d_in[15];
    const int* qwords = (const int*)d_in[16];

    int NW = in_sizes[0] / 64;
    int Q = in_sizes[1] / 64;
    int N = in_sizes[2] / 64;
    int R = in_sizes[9];
    int E = in_sizes[10];
    int B = in_sizes[13];

    zero_kernel<<<2048, 256>>>(N);
    precompute_P<<<64, 256>>>(Wv, Wo);
    prep_needed<<<(3 * B * 32 + 255) / 256, 256>>>(users, items, negs, B);

    {
        int smem = 49152 + 33792;   // 82944 B -> 2 CTAs/SM
        cudaFuncSetAttribute(fuse_zqk, cudaFuncAttributeMaxDynamicSharedMemorySize, smem);
        fuse_zqk<<<592, 384, smem>>>(W_word, Wq, Wk, NW);
    }

    edge_scan_kernel<<<(E + 255) / 256, 256>>>(p_src, p_dst, E);

    attn_kernel<<<1184, 256>>>(qids, rids, qwords, pdst, Q, R, B);

    build_kernel<<<(N * 32 + 255) / 256, 256>>>(W_query, W_entity, Q, N);

    edge_apply_kernel<<<1024, 256>>>(p_src, p_dst, p_qid);

    output_kernel<<<(3 * B * 32 + 255) / 256, 256>>>(users, items, negs, B, (float*)d_out);
}